// round 10
// baseline (speedup 1.0000x reference)
#include <cuda_runtime.h>
#include <cuda_bf16.h>
#include <cstdint>

#define NN 40000
#define EE 1280000

// ---------------- scratch (allocation-free) ----------------
__device__ float g_agg[NN * 64];
__device__ float g_aggc[NN * 3];
__device__ float g_cnt[NN];
__device__ float g_H1[NN * 64];   // h @ We1[0:64]  + be1
__device__ float g_H2[NN * 64];   // h @ We1[64:128]
__device__ int   g_idx64;

__device__ __forceinline__ float silu(float v) {
    return v * (1.0f / (1.0f + __expf(-v)));
}
// fast silu for the coord head only (result scaled by Wc2 ~ 3e-4)
__device__ __forceinline__ float silu_fast(float v) {
    float t;
    asm("tanh.approx.f32 %0, %1;" : "=f"(t) : "f"(v * 0.5f));
    return v * (0.5f * t + 0.5f);
}

__device__ __forceinline__ uint32_t pack_bf16x2(float lo_elem, float hi_elem) {
    uint32_t r;
    asm("cvt.rn.bf16x2.f32 %0, %1, %2;" : "=r"(r) : "f"(hi_elem), "f"(lo_elem));
    return r;
}
__device__ __forceinline__ void split_pair(float x, float y, uint32_t& hi, uint32_t& lo) {
    hi = pack_bf16x2(x, y);
    __nv_bfloat162 t;
    *reinterpret_cast<uint32_t*>(&t) = hi;
    lo = pack_bf16x2(x - __low2float(t), y - __high2float(t));
}

__device__ __forceinline__ void mma_bf16(float acc[4], uint32_t a0, uint32_t a1,
                                         uint32_t a2, uint32_t a3, uint32_t b0, uint32_t b1) {
    asm volatile(
        "mma.sync.aligned.m16n8k16.row.col.f32.bf16.bf16.f32 "
        "{%0,%1,%2,%3}, {%4,%5,%6,%7}, {%8,%9}, {%0,%1,%2,%3};"
        : "+f"(acc[0]), "+f"(acc[1]), "+f"(acc[2]), "+f"(acc[3])
        : "r"(a0), "r"(a1), "r"(a2), "r"(a3), "r"(b0), "r"(b1));
}

// column permutation: slot s -> real column, chosen so that acc pairs from
// n-tiles (2t, 2t+1) cover 4 contiguous real columns per lane (enables red.v4)
__device__ __forceinline__ int permcol(int s) {
    int a = s >> 3, c = s & 7;
    return 16 * (a >> 1) + 4 * (c >> 1) + 2 * (a & 1) + (c & 1);
}

// ---------------- zero + dtype detect ----------------
__global__ void zero_kernel(const int* __restrict__ ei32) {
    int i = blockIdx.x * blockDim.x + threadIdx.x;
    int stride = gridDim.x * blockDim.x;
    for (int k = i; k < NN * 64; k += stride) g_agg[k] = 0.f;
    for (int k = i; k < NN * 3;  k += stride) g_aggc[k] = 0.f;
    for (int k = i; k < NN;      k += stride) g_cnt[k] = 0.f;
    if (i == 0) {
        int all_zero = 1;
        #pragma unroll
        for (int k = 1; k < 64; k += 2) all_zero &= (ei32[k] == 0);
        g_idx64 = all_zero;
    }
}

// ---------------- hprep: H1 = h@We1_top + be1, H2 = h@We1_bot (HMMA, 3-term) ----------------
// smem words: W1H 0..4607 (128n x 36), W1L 4608..9215, BE1 9216..9279, per-warp A at 9280 (1152 ea)
#define HP_SMEM_BYTES ((9280 + 8 * 1152) * 4)

__global__ void __launch_bounds__(256, 2)
hprep_kernel(const float* __restrict__ h, const float* __restrict__ We1,
             const float* __restrict__ be1)
{
    extern __shared__ uint32_t smw[];
    float* smf = (float*)smw;
    int tid = threadIdx.x;
    for (int idx = tid; idx < 8192; idx += 256) {
        int n = idx & 127, k = idx >> 7;
        float v = We1[(k + ((n >= 64) ? 64 : 0)) * 64 + (n & 63)];
        __nv_bfloat16 hb = __float2bfloat16(v);
        ((__nv_bfloat16*)(smw))[n * 72 + k] = hb;
        ((__nv_bfloat16*)(smw + 4608))[n * 72 + k] = __float2bfloat16(v - __bfloat162float(hb));
    }
    if (tid < 64) smf[9216 + tid] = be1[tid];
    __syncthreads();

    int lane = tid & 31, warp = tid >> 5;
    uint32_t* AH = smw + 9280 + warp * 1152;
    uint32_t* AL = AH + 576;
    const int r0 = lane >> 2, q = lane & 3;
    const int le = lane >> 1, half = lane & 1;
    int nwarp = gridDim.x * 8;

    for (int t = blockIdx.x * 8 + warp; t < NN / 16; t += nwarp) {
        int node = t * 16 + le;
        const float4* p = (const float4*)(h + (size_t)node * 64 + half * 32);
        #pragma unroll
        for (int i = 0; i < 8; i++) {
            float4 u = p[i];
            uint32_t h0, l0, h1, l1;
            split_pair(u.x, u.y, h0, l0);
            split_pair(u.z, u.w, h1, l1);
            int off = le * 36 + half * 16 + i * 2;
            AH[off] = h0; AH[off + 1] = h1;
            AL[off] = l0; AL[off + 1] = l1;
        }
        __syncwarp();

        float acc[16][4];
        #pragma unroll
        for (int nt = 0; nt < 16; nt++)
            acc[nt][0] = acc[nt][1] = acc[nt][2] = acc[nt][3] = 0.f;
        #pragma unroll
        for (int ks = 0; ks < 4; ks++) {
            int abase = r0 * 36 + ks * 8 + q;
            uint32_t ah0 = AH[abase],     ah1 = AH[abase + 288];
            uint32_t ah2 = AH[abase + 4], ah3 = AH[abase + 292];
            uint32_t al0 = AL[abase],     al1 = AL[abase + 288];
            uint32_t al2 = AL[abase + 4], al3 = AL[abase + 292];
            #pragma unroll
            for (int nt = 0; nt < 16; nt++) {
                int bw = (nt * 8 + r0) * 36 + ks * 8 + q;
                uint32_t bh0 = smw[bw],        bh1 = smw[bw + 4];
                uint32_t bl0 = smw[4608 + bw], bl1 = smw[4608 + bw + 4];
                mma_bf16(acc[nt], ah0, ah1, ah2, ah3, bh0, bh1);
                mma_bf16(acc[nt], al0, al1, al2, al3, bh0, bh1);
                mma_bf16(acc[nt], ah0, ah1, ah2, ah3, bl0, bl1);
            }
        }
        int n0 = t * 16 + r0, n1 = n0 + 8;
        #pragma unroll
        for (int nt = 0; nt < 8; nt++) {
            int col = nt * 8 + 2 * q;
            float b0 = smf[9216 + col], b1 = smf[9216 + col + 1];
            ((float2*)g_H1)[(size_t)n0 * 32 + nt * 4 + q] = make_float2(acc[nt][0] + b0, acc[nt][1] + b1);
            ((float2*)g_H1)[(size_t)n1 * 32 + nt * 4 + q] = make_float2(acc[nt][2] + b0, acc[nt][3] + b1);
        }
        #pragma unroll
        for (int nt = 8; nt < 16; nt++) {
            int w = (nt - 8) * 4 + q;
            ((float2*)g_H2)[(size_t)n0 * 32 + w] = make_float2(acc[nt][0], acc[nt][1]);
            ((float2*)g_H2)[(size_t)n1 * 32 + w] = make_float2(acc[nt][2], acc[nt][3]);
        }
        __syncwarp();
    }
}

// ---------------- edge mega-kernel: warp-per-16-edges, HMMA ----------------
#define RSTR 36
#define W2H_OFF 0
#define W2L_OFF 2304
#define WCH_OFF 4608
#define BE2_OFF 6912
#define BC1_OFF 6976
#define WC2_OFF 7040
#define W128_OFF 7104
#define PW_OFF  7168
#define PW_SIZE 1808
#define SM_EDGE_BYTES ((PW_OFF + 16 * PW_SIZE) * 4)   // 144384

__global__ void __launch_bounds__(512, 1)
edge_kernel(const float* __restrict__ coord,
            const void* __restrict__ ei_raw, const float* __restrict__ emask,
            const float* __restrict__ We1, const float* __restrict__ We2,
            const float* __restrict__ be2, const float* __restrict__ Wc1,
            const float* __restrict__ bc1, const float* __restrict__ Wc2)
{
    extern __shared__ uint32_t smw[];
    float* smf = (float*)smw;
    int tid = threadIdx.x;

    // stage weights: W2 columns permuted by permcol (red.v4 layout);
    // Wc1's K rows permuted identically (GEMM3 consumes m in slot order)
    for (int idx = tid; idx < 4096; idx += 512) {
        int n = idx & 63, k = idx >> 6;
        float v = We2[k * 64 + permcol(n)];
        __nv_bfloat16 hb = __float2bfloat16(v);
        ((__nv_bfloat16*)(smw + W2H_OFF))[n * 72 + k] = hb;
        ((__nv_bfloat16*)(smw + W2L_OFF))[n * 72 + k] = __float2bfloat16(v - __bfloat162float(hb));
        ((__nv_bfloat16*)(smw + WCH_OFF))[n * 72 + k] = __float2bfloat16(Wc1[permcol(k) * 64 + n]);
    }
    if (tid < 64) {
        smf[BE2_OFF + tid]  = be2[permcol(tid)];
        smf[BC1_OFF + tid]  = bc1[tid];
        smf[WC2_OFF + tid]  = Wc2[tid];
        smf[W128_OFF + tid] = We1[128 * 64 + tid];
    }
    __syncthreads();

    const int is64 = g_idx64;
    const long long* ei64 = (const long long*)ei_raw;
    const int*       ei32 = (const int*)ei_raw;

    int lane = tid & 31, warp = tid >> 5;
    uint32_t* pw   = smw + PW_OFF + warp * PW_SIZE;
    uint32_t* A2H  = pw;
    uint32_t* A2L  = pw + 576;
    uint32_t* A3H  = pw + 1152;
    float*    sMSK = (float*)(pw + 1728);
    float*    sDX  = (float*)(pw + 1744);
    float*    sDY  = (float*)(pw + 1760);
    float*    sDZ  = (float*)(pw + 1776);
    int*      sRI  = (int*)(pw + 1792);

    const float* be2s = smf + BE2_OFF;
    const float* bc1s = smf + BC1_OFF;
    const float* wc2s = smf + WC2_OFF;
    const float* w128 = smf + W128_OFF;

    int gw = blockIdx.x * 16 + warp;
    const int r0 = lane >> 2, q = lane & 3;
    const int le = lane >> 1, half = lane & 1;

    for (int g = gw; g < EE / 16; g += 148 * 16) {
        int e = g * 16 + le;
        int ri, ci;
        if (is64) { ri = (int)ei64[e]; ci = (int)ei64[EE + e]; }
        else      { ri = ei32[e];      ci = ei32[EE + e]; }
        float msk = emask[e];
        float dx = coord[ri * 3 + 0] - coord[ci * 3 + 0];
        float dy = coord[ri * 3 + 1] - coord[ci * 3 + 1];
        float dz = coord[ri * 3 + 2] - coord[ci * 3 + 2];
        float radial = dx * dx + dy * dy + dz * dz;
        if (!half) { sMSK[le] = msk; sDX[le] = dx; sDY[le] = dy; sDZ[le] = dz; sRI[le] = ri; }

        // gather + exact layer-1 + silu + bf16 split -> A2
        const float4* p1 = (const float4*)(g_H1 + (size_t)ri * 64 + half * 32);
        const float4* p2 = (const float4*)(g_H2 + (size_t)ci * 64 + half * 32);
        #pragma unroll
        for (int i = 0; i < 8; i++) {
            float4 u = p1[i], v = p2[i];
            int cb = half * 32 + i * 4;
            float x0 = silu(u.x + v.x + radial * w128[cb + 0]);
            float x1 = silu(u.y + v.y + radial * w128[cb + 1]);
            float x2 = silu(u.z + v.z + radial * w128[cb + 2]);
            float x3 = silu(u.w + v.w + radial * w128[cb + 3]);
            uint32_t h0, l0, h1, l1;
            split_pair(x0, x1, h0, l0);
            split_pair(x2, x3, h1, l1);
            int off = le * RSTR + half * 16 + i * 2;
            A2H[off] = h0; A2H[off + 1] = h1;
            A2L[off] = l0; A2L[off + 1] = l1;
        }
        __syncwarp();

        // ---- GEMM2: [16x64] = A2 (3-term bf16) x W2^T (permuted cols) ----
        float acc[8][4];
        #pragma unroll
        for (int nt = 0; nt < 8; nt++)
            acc[nt][0] = acc[nt][1] = acc[nt][2] = acc[nt][3] = 0.f;
        #pragma unroll
        for (int ks = 0; ks < 4; ks++) {
            int abase = r0 * RSTR + ks * 8 + q;
            uint32_t ah0 = A2H[abase],     ah1 = A2H[abase + 8 * RSTR];
            uint32_t ah2 = A2H[abase + 4], ah3 = A2H[abase + 8 * RSTR + 4];
            uint32_t al0 = A2L[abase],     al1 = A2L[abase + 8 * RSTR];
            uint32_t al2 = A2L[abase + 4], al3 = A2L[abase + 8 * RSTR + 4];
            #pragma unroll
            for (int nt = 0; nt < 8; nt++) {
                int bw = (nt * 8 + r0) * RSTR + ks * 8 + q;
                uint32_t bh0 = smw[W2H_OFF + bw], bh1 = smw[W2H_OFF + bw + 4];
                uint32_t bl0 = smw[W2L_OFF + bw], bl1 = smw[W2L_OFF + bw + 4];
                mma_bf16(acc[nt], ah0, ah1, ah2, ah3, bh0, bh1);
                mma_bf16(acc[nt], al0, al1, al2, al3, bh0, bh1);
                mma_bf16(acc[nt], ah0, ah1, ah2, ah3, bl0, bl1);
            }
        }

        // ---- epilogue2: m = silu(+be2)*mask; red.v4 to g_agg; m(hi) -> A3 (slot order) ----
        float mk0 = sMSK[r0], mk1 = sMSK[r0 + 8];
        int   rn0 = sRI[r0],  rn1 = sRI[r0 + 8];
        #pragma unroll
        for (int t = 0; t < 4; t++) {
            int a0i = 2 * t, a1i = 2 * t + 1;
            int s00 = a0i * 8 + 2 * q, s10 = a1i * 8 + 2 * q;
            float u0 = silu(acc[a0i][0] + be2s[s00])     * mk0;
            float u1 = silu(acc[a0i][1] + be2s[s00 + 1]) * mk0;
            float u2 = silu(acc[a1i][0] + be2s[s10])     * mk0;
            float u3 = silu(acc[a1i][1] + be2s[s10 + 1]) * mk0;
            float w0 = silu(acc[a0i][2] + be2s[s00])     * mk1;
            float w1 = silu(acc[a0i][3] + be2s[s00 + 1]) * mk1;
            float w2 = silu(acc[a1i][2] + be2s[s10])     * mk1;
            float w3 = silu(acc[a1i][3] + be2s[s10 + 1]) * mk1;
            // real cols 16t+4q .. +3 (by construction of permcol)
            asm volatile("red.global.add.v4.f32 [%0], {%1, %2, %3, %4};"
                         :: "l"(&g_agg[(size_t)rn0 * 64 + 16 * t + 4 * q]),
                            "f"(u0), "f"(u1), "f"(u2), "f"(u3) : "memory");
            asm volatile("red.global.add.v4.f32 [%0], {%1, %2, %3, %4};"
                         :: "l"(&g_agg[(size_t)rn1 * 64 + 16 * t + 4 * q]),
                            "f"(w0), "f"(w1), "f"(w2), "f"(w3) : "memory");
            A3H[r0 * RSTR + a0i * 4 + q]       = pack_bf16x2(u0, u1);
            A3H[r0 * RSTR + a1i * 4 + q]       = pack_bf16x2(u2, u3);
            A3H[(r0 + 8) * RSTR + a0i * 4 + q] = pack_bf16x2(w0, w1);
            A3H[(r0 + 8) * RSTR + a1i * 4 + q] = pack_bf16x2(w2, w3);
        }
        __syncwarp();

        // ---- GEMM3: [16x64] = A3 (1-term bf16, slot-k) x Wc1^T (k-permuted) ----
        #pragma unroll
        for (int nt = 0; nt < 8; nt++)
            acc[nt][0] = acc[nt][1] = acc[nt][2] = acc[nt][3] = 0.f;
        #pragma unroll
        for (int ks = 0; ks < 4; ks++) {
            int abase = r0 * RSTR + ks * 8 + q;
            uint32_t a0 = A3H[abase],     a1 = A3H[abase + 8 * RSTR];
            uint32_t a2 = A3H[abase + 4], a3 = A3H[abase + 8 * RSTR + 4];
            #pragma unroll
            for (int nt = 0; nt < 8; nt++) {
                int bw = (nt * 8 + r0) * RSTR + ks * 8 + q;
                mma_bf16(acc[nt], a0, a1, a2, a3, smw[WCH_OFF + bw], smw[WCH_OFF + bw + 4]);
            }
        }

        // ---- epilogue3: c = silu(+bc1)@Wc2; coord atomics ----
        float s0 = 0.f, s1 = 0.f;
        #pragma unroll
        for (int nt = 0; nt < 8; nt++) {
            int col = nt * 8 + 2 * q;
            s0 += silu_fast(acc[nt][0] + bc1s[col]) * wc2s[col]
                + silu_fast(acc[nt][1] + bc1s[col + 1]) * wc2s[col + 1];
            s1 += silu_fast(acc[nt][2] + bc1s[col]) * wc2s[col]
                + silu_fast(acc[nt][3] + bc1s[col + 1]) * wc2s[col + 1];
        }
        s0 += __shfl_xor_sync(0xffffffffu, s0, 1);
        s0 += __shfl_xor_sync(0xffffffffu, s0, 2);
        s1 += __shfl_xor_sync(0xffffffffu, s1, 1);
        s1 += __shfl_xor_sync(0xffffffffu, s1, 2);
        if (q == 0) {
            float cc0 = s0 * mk0;
            atomicAdd(&g_aggc[(size_t)rn0 * 3 + 0], sDX[r0] * cc0);
            atomicAdd(&g_aggc[(size_t)rn0 * 3 + 1], sDY[r0] * cc0);
            atomicAdd(&g_aggc[(size_t)rn0 * 3 + 2], sDZ[r0] * cc0);
            atomicAdd(&g_cnt[rn0], 1.0f);
            float cc1 = s1 * mk1;
            atomicAdd(&g_aggc[(size_t)rn1 * 3 + 0], sDX[r0 + 8] * cc1);
            atomicAdd(&g_aggc[(size_t)rn1 * 3 + 1], sDY[r0 + 8] * cc1);
            atomicAdd(&g_aggc[(size_t)rn1 * 3 + 2], sDZ[r0 + 8] * cc1);
            atomicAdd(&g_cnt[rn1], 1.0f);
        }
        __syncwarp();
    }
}

// ---------------- node kernel (HMMA, 3-term both GEMMs) ----------------
// smem words: W1H 0 (64x68=4352), W1L 4352, W2H 8704 (2304), W2L 11008,
// BN1 13312, BN2 13376, per-warp 13440 (+3328 each: A1H 0, A1L 1088, A2H 2176, A2L 2752)
#define ND_PW 13440
#define ND_SMEM_BYTES ((ND_PW + 8 * 3328) * 4)   // 160256

__global__ void __launch_bounds__(256, 1)
node_kernel(const float* __restrict__ h, const float* __restrict__ coord,
            const float* __restrict__ Wn1, const float* __restrict__ bn1,
            const float* __restrict__ Wn2, const float* __restrict__ bn2,
            float* __restrict__ hout, float* __restrict__ cout)
{
    extern __shared__ uint32_t smw[];
    float* smf = (float*)smw;
    int tid = threadIdx.x;

    for (int idx = tid; idx < 8192; idx += 256) {
        int n = idx & 63, k = idx >> 6;
        float v = Wn1[k * 64 + n];
        __nv_bfloat16 hb = __float2bfloat16(v);
        ((__nv_bfloat16*)(smw))[n * 136 + k] = hb;
        ((__nv_bfloat16*)(smw + 4352))[n * 136 + k] = __float2bfloat16(v - __bfloat162float(hb));
    }
    for (int idx = tid; idx < 4096; idx += 256) {
        int n = idx & 63, k = idx >> 6;
        float v = Wn2[k * 64 + n];
        __nv_bfloat16 hb = __float2bfloat16(v);
        ((__nv_bfloat16*)(smw + 8704))[n * 72 + k] = hb;
        ((__nv_bfloat16*)(smw + 11008))[n * 72 + k] = __float2bfloat16(v - __bfloat162float(hb));
    }
    if (tid < 64) { smf[13312 + tid] = bn1[tid]; smf[13376 + tid] = bn2[tid]; }
    __syncthreads();

    int lane = tid & 31, warp = tid >> 5;
    uint32_t* A1H = smw + ND_PW + warp * 3328;
    uint32_t* A1L = A1H + 1088;
    uint32_t* A2H = A1H + 2176;
    uint32_t* A2L = A1H + 2752;
    const int r0 = lane >> 2, q = lane & 3;
    const int le = lane >> 1, half = lane & 1;
    int nwarp = gridDim.x * 8;

    for (int t = blockIdx.x * 8 + warp; t < NN / 16; t += nwarp) {
        int node = t * 16 + le;
        const float4* ph = (const float4*)(h + (size_t)node * 64 + half * 32);
        const float4* pa = (const float4*)(g_agg + (size_t)node * 64 + half * 32);
        #pragma unroll
        for (int i = 0; i < 8; i++) {
            float4 u = ph[i];
            uint32_t h0, l0, h1, l1;
            split_pair(u.x, u.y, h0, l0);
            split_pair(u.z, u.w, h1, l1);
            int off = le * 68 + half * 16 + i * 2;
            A1H[off] = h0; A1H[off + 1] = h1;
            A1L[off] = l0; A1L[off + 1] = l1;
            float4 v = pa[i];
            split_pair(v.x, v.y, h0, l0);
            split_pair(v.z, v.w, h1, l1);
            off += 32;
            A1H[off] = h0; A1H[off + 1] = h1;
            A1L[off] = l0; A1L[off + 1] = l1;
        }
        __syncwarp();

        // GEMM1: K=128, 3-term
        float acc[8][4];
        #pragma unroll
        for (int nt = 0; nt < 8; nt++)
            acc[nt][0] = acc[nt][1] = acc[nt][2] = acc[nt][3] = 0.f;
        #pragma unroll
        for (int ks = 0; ks < 8; ks++) {
            int abase = r0 * 68 + ks * 8 + q;
            uint32_t ah0 = A1H[abase],     ah1 = A1H[abase + 544];
            uint32_t ah2 = A1H[abase + 4], ah3 = A1H[abase + 548];
            uint32_t al0 = A1L[abase],     al1 = A1L[abase + 544];
            uint32_t al2 = A1L[abase + 4], al3 = A1L[abase + 548];
            #pragma unroll
            for (int nt = 0; nt < 8; nt++) {
                int bw = (nt * 8 + r0) * 68 + ks * 8 + q;
                uint32_t bh0 = smw[bw],        bh1 = smw[bw + 4];
                uint32_t bl0 = smw[4352 + bw], bl1 = smw[4352 + bw + 4];
                mma_bf16(acc[nt], ah0, ah1, ah2, ah3, bh0, bh1);
                mma_bf16(acc[nt], al0, al1, al2, al3, bh0, bh1);
                mma_bf16(acc[nt], ah0, ah1, ah2, ah3, bl0, bl1);
            }
        }
        // epilogue1: silu -> A2 (hi/lo)
        #pragma unroll
        for (int nt = 0; nt < 8; nt++) {
            int col = nt * 8 + 2 * q;
            float b0 = smf[13312 + col], b1 = smf[13312 + col + 1];
            uint32_t hp, lp;
            split_pair(silu(acc[nt][0] + b0), silu(acc[nt][1] + b1), hp, lp);
            A2H[r0 * 36 + nt * 4 + q] = hp; A2L[r0 * 36 + nt * 4 + q] = lp;
            split_pair(silu(acc[nt][2] + b0), silu(acc[nt][3] + b1), hp, lp);
            A2H[(r0 + 8) * 36 + nt * 4 + q] = hp; A2L[(r0 + 8) * 36 + nt * 4 + q] = lp;
        }
        __syncwarp();

        // GEMM2: K=64, 3-term
        #pragma unroll
        for (int nt = 0; nt < 8; nt++)
            acc[nt][0] = acc[nt][1] = acc[nt][2] = acc[nt][3] = 0.f;
        #pragma unroll
        for (int ks = 0; ks < 4; ks++) {
            int abase = r0 * 36 + ks * 8 + q;
            uint32_t ah0 = A2H[abase],     ah1 = A2H[abase + 288];
            uint32_t ah2 = A2H[abase + 4], ah3 = A2H[abase + 292];
            uint32_t al0 = A2L[abase],     al1 = A2L[abase + 288];
            uint32_t al2 = A2L[abase + 4], al3 = A2L[abase + 292];
            #pragma unroll
            for (int nt = 0; nt < 8; nt++) {
                int bw = (nt * 8 + r0) * 36 + ks * 8 + q;
                uint32_t bh0 = smw[8704 + bw],  bh1 = smw[8704 + bw + 4];
                uint32_t bl0 = smw[11008 + bw], bl1 = smw[11008 + bw + 4];
                mma_bf16(acc[nt], ah0, ah1, ah2, ah3, bh0, bh1);
                mma_bf16(acc[nt], al0, al1, al2, al3, bh0, bh1);
                mma_bf16(acc[nt], ah0, ah1, ah2, ah3, bl0, bl1);
            }
        }
        int n0 = t * 16 + r0, n1 = n0 + 8;
        #pragma unroll
        for (int nt = 0; nt < 8; nt++) {
            int col = nt * 8 + 2 * q;
            float b0 = smf[13376 + col], b1 = smf[13376 + col + 1];
            ((float2*)hout)[(size_t)n0 * 32 + nt * 4 + q] = make_float2(acc[nt][0] + b0, acc[nt][1] + b1);
            ((float2*)hout)[(size_t)n1 * 32 + nt * 4 + q] = make_float2(acc[nt][2] + b0, acc[nt][3] + b1);
        }
        // coord epilogue: 16 nodes by lanes 0..15
        if (lane < 16) {
            int n = t * 16 + lane;
            float cnt = g_cnt[n];
            cnt = cnt > 1.f ? cnt : 1.f;
            float inv = 1.f / cnt;
            cout[n * 3 + 0] = coord[n * 3 + 0] + g_aggc[n * 3 + 0] * inv;
            cout[n * 3 + 1] = coord[n * 3 + 1] + g_aggc[n * 3 + 1] * inv;
            cout[n * 3 + 2] = coord[n * 3 + 2] + g_aggc[n * 3 + 2] * inv;
        }
        __syncwarp();
    }
}

extern "C" void kernel_launch(void* const* d_in, const int* in_sizes, int n_in,
                              void* d_out, int out_size)
{
    const float* h     = (const float*)d_in[0];
    const float* coord = (const float*)d_in[1];
    const void*  ei    = d_in[2];
    const float* emask = (const float*)d_in[3];
    const float* We1 = (const float*)d_in[4];  const float* be1 = (const float*)d_in[5];
    const float* We2 = (const float*)d_in[6];  const float* be2 = (const float*)d_in[7];
    const float* Wn1 = (const float*)d_in[8];  const float* bn1 = (const float*)d_in[9];
    const float* Wn2 = (const float*)d_in[10]; const float* bn2 = (const float*)d_in[11];
    const float* Wc1 = (const float*)d_in[12]; const float* bc1 = (const float*)d_in[13];
    const float* Wc2 = (const float*)d_in[14];

    float* hout = (float*)d_out;
    float* cout = hout + (size_t)NN * 64;

    cudaFuncSetAttribute(hprep_kernel, cudaFuncAttributeMaxDynamicSharedMemorySize, HP_SMEM_BYTES);
    cudaFuncSetAttribute(edge_kernel, cudaFuncAttributeMaxDynamicSharedMemorySize, SM_EDGE_BYTES);
    cudaFuncSetAttribute(node_kernel, cudaFuncAttributeMaxDynamicSharedMemorySize, ND_SMEM_BYTES);

    zero_kernel<<<2048, 256>>>((const int*)ei);
    hprep_kernel<<<296, 256, HP_SMEM_BYTES>>>(h, We1, be1);
    edge_kernel<<<148, 512, SM_EDGE_BYTES>>>(coord, ei, emask, We1, We2, be2, Wc1, bc1, Wc2);
    node_kernel<<<148, 256, ND_SMEM_BYTES>>>(h, coord, Wn1, bn1, Wn2, bn2, hout, cout);
}

// round 13
// speedup vs baseline: 1.1957x; 1.1957x over previous
#include <cuda_runtime.h>
#include <cuda_bf16.h>
#include <cstdint>

#define NN 40000
#define EE 1280000
#define WTILES (EE / 16)

// ---------------- scratch (allocation-free) ----------------
__device__ float g_agg[NN * 64];
__device__ float g_aggc[NN * 3];
__device__ float g_H1[NN * 64];   // h @ We1[0:64]  + be1
__device__ float g_H2[NN * 64];   // h @ We1[64:128]
__device__ int   g_hist[NN];      // edges per row (== cnt)
__device__ int   g_start[NN];     // unused after scan (kept for clarity)
__device__ int   g_cursor[NN];    // scatter cursors
__device__ int   g_sorted[EE];    // edge ids sorted by row
__device__ int   g_idx64;

__device__ __forceinline__ float silu(float v) {
    return v * (1.0f / (1.0f + __expf(-v)));
}

__device__ __forceinline__ uint32_t pack_bf16x2(float lo_elem, float hi_elem) {
    uint32_t r;
    asm("cvt.rn.bf16x2.f32 %0, %1, %2;" : "=r"(r) : "f"(hi_elem), "f"(lo_elem));
    return r;
}
__device__ __forceinline__ void split_pair(float x, float y, uint32_t& hi, uint32_t& lo) {
    hi = pack_bf16x2(x, y);
    __nv_bfloat162 t;
    *reinterpret_cast<uint32_t*>(&t) = hi;
    lo = pack_bf16x2(x - __low2float(t), y - __high2float(t));
}

__device__ __forceinline__ void mma_bf16(float acc[4], uint32_t a0, uint32_t a1,
                                         uint32_t a2, uint32_t a3, uint32_t b0, uint32_t b1) {
    asm volatile(
        "mma.sync.aligned.m16n8k16.row.col.f32.bf16.bf16.f32 "
        "{%0,%1,%2,%3}, {%4,%5,%6,%7}, {%8,%9}, {%0,%1,%2,%3};"
        : "+f"(acc[0]), "+f"(acc[1]), "+f"(acc[2]), "+f"(acc[3])
        : "r"(a0), "r"(a1), "r"(a2), "r"(a3), "r"(b0), "r"(b1));
}

__device__ __forceinline__ int edge_row(const void* ei_raw, int e, int is64) {
    return is64 ? (int)((const long long*)ei_raw)[e] : ((const int*)ei_raw)[e];
}
__device__ __forceinline__ int edge_col(const void* ei_raw, int e, int is64) {
    return is64 ? (int)((const long long*)ei_raw)[EE + e] : ((const int*)ei_raw)[EE + e];
}

// ---------------- zero + dtype detect ----------------
__global__ void zero_kernel(const int* __restrict__ ei32) {
    int i = blockIdx.x * blockDim.x + threadIdx.x;
    int stride = gridDim.x * blockDim.x;
    for (int k = i; k < NN * 64; k += stride) g_agg[k] = 0.f;
    for (int k = i; k < NN * 3;  k += stride) g_aggc[k] = 0.f;
    for (int k = i; k < NN;      k += stride) g_hist[k] = 0;
    if (i == 0) {
        int all_zero = 1;
        #pragma unroll
        for (int k = 1; k < 64; k += 2) all_zero &= (ei32[k] == 0);
        g_idx64 = all_zero;
    }
}

// ---------------- counting sort ----------------
__global__ void hist_kernel(const void* __restrict__ ei_raw) {
    int is64 = g_idx64;
    int i = blockIdx.x * blockDim.x + threadIdx.x;
    int stride = gridDim.x * blockDim.x;
    for (int e = i; e < EE; e += stride)
        atomicAdd(&g_hist[edge_row(ei_raw, e, is64)], 1);
}

// one block, 1024 threads: exclusive scan of g_hist -> g_cursor
__global__ void scan_kernel() {
    __shared__ int ssum[1024];
    int t = threadIdx.x;
    int base = t * 40;
    int loc[40];
    int s = 0;
    #pragma unroll
    for (int i = 0; i < 40; i++) {
        int idx = base + i;
        int v = (idx < NN) ? g_hist[idx] : 0;
        loc[i] = s;
        s += v;
    }
    ssum[t] = s;
    __syncthreads();
    for (int off = 1; off < 1024; off <<= 1) {
        int v = (t >= off) ? ssum[t - off] : 0;
        __syncthreads();
        ssum[t] += v;
        __syncthreads();
    }
    int excl = ssum[t] - s;
    #pragma unroll
    for (int i = 0; i < 40; i++) {
        int idx = base + i;
        if (idx < NN) { g_start[idx] = excl + loc[i]; g_cursor[idx] = excl + loc[i]; }
    }
}

__global__ void scatter_kernel(const void* __restrict__ ei_raw) {
    int is64 = g_idx64;
    int i = blockIdx.x * blockDim.x + threadIdx.x;
    int stride = gridDim.x * blockDim.x;
    for (int e = i; e < EE; e += stride) {
        int r = edge_row(ei_raw, e, is64);
        int pos = atomicAdd(&g_cursor[r], 1);
        g_sorted[pos] = e;
    }
}

// ---------------- hprep: H1 = h@We1_top + be1, H2 = h@We1_bot (HMMA, 3-term) ----------------
#define HP_SMEM_BYTES ((9280 + 8 * 1152) * 4)

__global__ void __launch_bounds__(256, 2)
hprep_kernel(const float* __restrict__ h, const float* __restrict__ We1,
             const float* __restrict__ be1)
{
    extern __shared__ uint32_t smw[];
    float* smf = (float*)smw;
    int tid = threadIdx.x;
    for (int idx = tid; idx < 8192; idx += 256) {
        int n = idx & 127, k = idx >> 7;
        float v = We1[(k + ((n >= 64) ? 64 : 0)) * 64 + (n & 63)];
        __nv_bfloat16 hb = __float2bfloat16(v);
        ((__nv_bfloat16*)(smw))[n * 72 + k] = hb;
        ((__nv_bfloat16*)(smw + 4608))[n * 72 + k] = __float2bfloat16(v - __bfloat162float(hb));
    }
    if (tid < 64) smf[9216 + tid] = be1[tid];
    __syncthreads();

    int lane = tid & 31, warp = tid >> 5;
    uint32_t* AH = smw + 9280 + warp * 1152;
    uint32_t* AL = AH + 576;
    const int r0 = lane >> 2, q = lane & 3;
    const int le = lane >> 1, half = lane & 1;
    int nwarp = gridDim.x * 8;

    for (int t = blockIdx.x * 8 + warp; t < NN / 16; t += nwarp) {
        int node = t * 16 + le;
        const float4* p = (const float4*)(h + (size_t)node * 64 + half * 32);
        #pragma unroll
        for (int i = 0; i < 8; i++) {
            float4 u = p[i];
            uint32_t h0, l0, h1, l1;
            split_pair(u.x, u.y, h0, l0);
            split_pair(u.z, u.w, h1, l1);
            int off = le * 36 + half * 16 + i * 2;
            AH[off] = h0; AH[off + 1] = h1;
            AL[off] = l0; AL[off + 1] = l1;
        }
        __syncwarp();

        float acc[16][4];
        #pragma unroll
        for (int nt = 0; nt < 16; nt++)
            acc[nt][0] = acc[nt][1] = acc[nt][2] = acc[nt][3] = 0.f;
        #pragma unroll
        for (int ks = 0; ks < 4; ks++) {
            int abase = r0 * 36 + ks * 8 + q;
            uint32_t ah0 = AH[abase],     ah1 = AH[abase + 288];
            uint32_t ah2 = AH[abase + 4], ah3 = AH[abase + 292];
            uint32_t al0 = AL[abase],     al1 = AL[abase + 288];
            uint32_t al2 = AL[abase + 4], al3 = AL[abase + 292];
            #pragma unroll
            for (int nt = 0; nt < 16; nt++) {
                int bw = (nt * 8 + r0) * 36 + ks * 8 + q;
                uint32_t bh0 = smw[bw],        bh1 = smw[bw + 4];
                uint32_t bl0 = smw[4608 + bw], bl1 = smw[4608 + bw + 4];
                mma_bf16(acc[nt], ah0, ah1, ah2, ah3, bh0, bh1);
                mma_bf16(acc[nt], al0, al1, al2, al3, bh0, bh1);
                mma_bf16(acc[nt], ah0, ah1, ah2, ah3, bl0, bl1);
            }
        }
        int n0 = t * 16 + r0, n1 = n0 + 8;
        #pragma unroll
        for (int nt = 0; nt < 8; nt++) {
            int col = nt * 8 + 2 * q;
            float b0 = smf[9216 + col], b1 = smf[9216 + col + 1];
            ((float2*)g_H1)[(size_t)n0 * 32 + nt * 4 + q] = make_float2(acc[nt][0] + b0, acc[nt][1] + b1);
            ((float2*)g_H1)[(size_t)n1 * 32 + nt * 4 + q] = make_float2(acc[nt][2] + b0, acc[nt][3] + b1);
        }
        #pragma unroll
        for (int nt = 8; nt < 16; nt++) {
            int w = (nt - 8) * 4 + q;
            ((float2*)g_H2)[(size_t)n0 * 32 + w] = make_float2(acc[nt][0], acc[nt][1]);
            ((float2*)g_H2)[(size_t)n1 * 32 + w] = make_float2(acc[nt][2], acc[nt][3]);
        }
        __syncwarp();
    }
}

// ---------------- edge mega-kernel: sorted edges, HMMA, segmented reduce ----------------
#define RSTR 36
#define W2H_OFF 0
#define W2L_OFF 2304
#define WCH_OFF 4608
#define BE2_OFF 6912
#define BC1_OFF 6976
#define WC2_OFF 7040
#define W128_OFF 7104
#define PW_OFF  7168
// per-warp: A2H 0..575, A2L 576..1151, M overlaps [0..1087] (f32, row stride 68),
// MSK 1152, DX 1168, DY 1184, DZ 1200, RI 1216  -> 1232 words
#define PW_SIZE 1232
#define SM_EDGE_BYTES ((PW_OFF + 16 * PW_SIZE) * 4)   // 107520

__global__ void __launch_bounds__(512, 1)
edge_kernel(const float* __restrict__ coord,
            const void* __restrict__ ei_raw, const float* __restrict__ emask,
            const float* __restrict__ We1, const float* __restrict__ We2,
            const float* __restrict__ be2, const float* __restrict__ Wc1,
            const float* __restrict__ bc1, const float* __restrict__ Wc2)
{
    extern __shared__ uint32_t smw[];
    float* smf = (float*)smw;
    int tid = threadIdx.x;

    for (int idx = tid; idx < 4096; idx += 512) {
        int n = idx & 63, k = idx >> 6;
        float v = We2[k * 64 + n];
        __nv_bfloat16 hb = __float2bfloat16(v);
        ((__nv_bfloat16*)(smw + W2H_OFF))[n * 72 + k] = hb;
        ((__nv_bfloat16*)(smw + W2L_OFF))[n * 72 + k] = __float2bfloat16(v - __bfloat162float(hb));
        ((__nv_bfloat16*)(smw + WCH_OFF))[n * 72 + k] = __float2bfloat16(Wc1[k * 64 + n]);
    }
    if (tid < 64) {
        smf[BE2_OFF + tid]  = be2[tid];
        smf[BC1_OFF + tid]  = bc1[tid];
        smf[WC2_OFF + tid]  = Wc2[tid];
        smf[W128_OFF + tid] = We1[128 * 64 + tid];
    }
    __syncthreads();

    const int is64 = g_idx64;

    int lane = tid & 31, warp = tid >> 5;
    uint32_t* pw   = smw + PW_OFF + warp * PW_SIZE;
    uint32_t* A2H  = pw;
    uint32_t* A2L  = pw + 576;
    float*    Mf   = (float*)pw;          // overlaps A2 (A2 dead when M written)
    float*    sMSK = (float*)(pw + 1152);
    float*    sDX  = (float*)(pw + 1168);
    float*    sDY  = (float*)(pw + 1184);
    float*    sDZ  = (float*)(pw + 1200);
    int*      sRI  = (int*)(pw + 1216);

    const float* be2s = smf + BE2_OFF;
    const float* bc1s = smf + BC1_OFF;
    const float* wc2s = smf + WC2_OFF;
    const float* w128 = smf + W128_OFF;

    const int r0 = lane >> 2, q = lane & 3;
    const int le = lane >> 1, half = lane & 1;

    for (int g = blockIdx.x * 16 + warp; g < WTILES; g += 148 * 16) {
        int e = g_sorted[g * 16 + le];
        int ri = edge_row(ei_raw, e, is64);
        int ci = edge_col(ei_raw, e, is64);
        float msk = emask[e];
        float dx = coord[ri * 3 + 0] - coord[ci * 3 + 0];
        float dy = coord[ri * 3 + 1] - coord[ci * 3 + 1];
        float dz = coord[ri * 3 + 2] - coord[ci * 3 + 2];
        float radial = dx * dx + dy * dy + dz * dz;
        if (!half) { sMSK[le] = msk; sDX[le] = dx; sDY[le] = dy; sDZ[le] = dz; sRI[le] = ri; }

        // gather + exact layer-1 + silu + bf16 split -> A2
        const float4* p1 = (const float4*)(g_H1 + (size_t)ri * 64 + half * 32);
        const float4* p2 = (const float4*)(g_H2 + (size_t)ci * 64 + half * 32);
        #pragma unroll
        for (int i = 0; i < 8; i++) {
            float4 u = p1[i], v = p2[i];
            int cb = half * 32 + i * 4;
            float x0 = silu(u.x + v.x + radial * w128[cb + 0]);
            float x1 = silu(u.y + v.y + radial * w128[cb + 1]);
            float x2 = silu(u.z + v.z + radial * w128[cb + 2]);
            float x3 = silu(u.w + v.w + radial * w128[cb + 3]);
            uint32_t h0, l0, h1, l1;
            split_pair(x0, x1, h0, l0);
            split_pair(x2, x3, h1, l1);
            int off = le * RSTR + half * 16 + i * 2;
            A2H[off] = h0; A2H[off + 1] = h1;
            A2L[off] = l0; A2L[off + 1] = l1;
        }
        __syncwarp();

        // ---- GEMM2: [16x64] = A2 (3-term bf16) x W2^T ----
        float acc[8][4];
        #pragma unroll
        for (int nt = 0; nt < 8; nt++)
            acc[nt][0] = acc[nt][1] = acc[nt][2] = acc[nt][3] = 0.f;
        #pragma unroll
        for (int ks = 0; ks < 4; ks++) {
            int abase = r0 * RSTR + ks * 8 + q;
            uint32_t ah0 = A2H[abase],     ah1 = A2H[abase + 8 * RSTR];
            uint32_t ah2 = A2H[abase + 4], ah3 = A2H[abase + 8 * RSTR + 4];
            uint32_t al0 = A2L[abase],     al1 = A2L[abase + 8 * RSTR];
            uint32_t al2 = A2L[abase + 4], al3 = A2L[abase + 8 * RSTR + 4];
            #pragma unroll
            for (int nt = 0; nt < 8; nt++) {
                int bw = (nt * 8 + r0) * RSTR + ks * 8 + q;
                uint32_t bh0 = smw[W2H_OFF + bw], bh1 = smw[W2H_OFF + bw + 4];
                uint32_t bl0 = smw[W2L_OFF + bw], bl1 = smw[W2L_OFF + bw + 4];
                mma_bf16(acc[nt], ah0, ah1, ah2, ah3, bh0, bh1);
                mma_bf16(acc[nt], al0, al1, al2, al3, bh0, bh1);
                mma_bf16(acc[nt], ah0, ah1, ah2, ah3, bl0, bl1);
            }
        }
        __syncwarp();   // A2 reads done; M may now overwrite the region

        // ---- epilogue2: m = silu(+be2)*mask -> M(smem f32) + af(registers for GEMM3) ----
        float mk0 = sMSK[r0], mk1 = sMSK[r0 + 8];
        uint32_t af[8][2];
        #pragma unroll
        for (int nt = 0; nt < 8; nt++) {
            int col = nt * 8 + 2 * q;
            float m00 = silu(acc[nt][0] + be2s[col])     * mk0;
            float m01 = silu(acc[nt][1] + be2s[col + 1]) * mk0;
            float m10 = silu(acc[nt][2] + be2s[col])     * mk1;
            float m11 = silu(acc[nt][3] + be2s[col + 1]) * mk1;
            af[nt][0] = pack_bf16x2(m00, m01);
            af[nt][1] = pack_bf16x2(m10, m11);
            *(float2*)&Mf[r0 * 68 + col]       = make_float2(m00, m01);
            *(float2*)&Mf[(r0 + 8) * 68 + col] = make_float2(m10, m11);
        }
        __syncwarp();

        // ---- segmented reduction over sorted rows: lane owns cols 2*lane..+1 ----
        {
            float2 sacc = make_float2(0.f, 0.f);
            int cur = sRI[0];
            #pragma unroll
            for (int i = 0; i < 16; i++) {
                float2 v = *(const float2*)&Mf[i * 68 + 2 * lane];
                sacc.x += v.x; sacc.y += v.y;
                int nxt = (i < 15) ? sRI[i + 1] : -1;
                if (nxt != cur) {
                    asm volatile("red.global.add.v2.f32 [%0], {%1, %2};"
                                 :: "l"(&g_agg[(size_t)cur * 64 + 2 * lane]),
                                    "f"(sacc.x), "f"(sacc.y) : "memory");
                    sacc.x = 0.f; sacc.y = 0.f;
                    cur = nxt;
                }
            }
        }

        // ---- GEMM3: [16x64] = m (registers, 1-term bf16) x Wc1^T ----
        #pragma unroll
        for (int nt = 0; nt < 8; nt++)
            acc[nt][0] = acc[nt][1] = acc[nt][2] = acc[nt][3] = 0.f;
        #pragma unroll
        for (int ks = 0; ks < 4; ks++) {
            uint32_t a0 = af[2 * ks][0],     a1 = af[2 * ks][1];
            uint32_t a2 = af[2 * ks + 1][0], a3 = af[2 * ks + 1][1];
            #pragma unroll
            for (int nt = 0; nt < 8; nt++) {
                int bw = (nt * 8 + r0) * RSTR + ks * 8 + q;
                mma_bf16(acc[nt], a0, a1, a2, a3, smw[WCH_OFF + bw], smw[WCH_OFF + bw + 4]);
            }
        }

        // ---- epilogue3: c = silu(+bc1)@Wc2; coord atomics ----
        float s0 = 0.f, s1 = 0.f;
        #pragma unroll
        for (int nt = 0; nt < 8; nt++) {
            int col = nt * 8 + 2 * q;
            s0 += silu(acc[nt][0] + bc1s[col]) * wc2s[col]
                + silu(acc[nt][1] + bc1s[col + 1]) * wc2s[col + 1];
            s1 += silu(acc[nt][2] + bc1s[col]) * wc2s[col]
                + silu(acc[nt][3] + bc1s[col + 1]) * wc2s[col + 1];
        }
        s0 += __shfl_xor_sync(0xffffffffu, s0, 1);
        s0 += __shfl_xor_sync(0xffffffffu, s0, 2);
        s1 += __shfl_xor_sync(0xffffffffu, s1, 1);
        s1 += __shfl_xor_sync(0xffffffffu, s1, 2);
        if (q == 0) {
            int rn0 = sRI[r0], rn1 = sRI[r0 + 8];
            float cc0 = s0 * mk0;
            atomicAdd(&g_aggc[(size_t)rn0 * 3 + 0], sDX[r0] * cc0);
            atomicAdd(&g_aggc[(size_t)rn0 * 3 + 1], sDY[r0] * cc0);
            atomicAdd(&g_aggc[(size_t)rn0 * 3 + 2], sDZ[r0] * cc0);
            float cc1 = s1 * mk1;
            atomicAdd(&g_aggc[(size_t)rn1 * 3 + 0], sDX[r0 + 8] * cc1);
            atomicAdd(&g_aggc[(size_t)rn1 * 3 + 1], sDY[r0 + 8] * cc1);
            atomicAdd(&g_aggc[(size_t)rn1 * 3 + 2], sDZ[r0 + 8] * cc1);
        }
        __syncwarp();
    }
}

// ---------------- node kernel (HMMA, 3-term both GEMMs) ----------------
#define ND_PW 13440
#define ND_SMEM_BYTES ((ND_PW + 8 * 3328) * 4)

__global__ void __launch_bounds__(256, 1)
node_kernel(const float* __restrict__ h, const float* __restrict__ coord,
            const float* __restrict__ Wn1, const float* __restrict__ bn1,
            const float* __restrict__ Wn2, const float* __restrict__ bn2,
            float* __restrict__ hout, float* __restrict__ cout)
{
    extern __shared__ uint32_t smw[];
    float* smf = (float*)smw;
    int tid = threadIdx.x;

    for (int idx = tid; idx < 8192; idx += 256) {
        int n = idx & 63, k = idx >> 6;
        float v = Wn1[k * 64 + n];
        __nv_bfloat16 hb = __float2bfloat16(v);
        ((__nv_bfloat16*)(smw))[n * 136 + k] = hb;
        ((__nv_bfloat16*)(smw + 4352))[n * 136 + k] = __float2bfloat16(v - __bfloat162float(hb));
    }
    for (int idx = tid; idx < 4096; idx += 256) {
        int n = idx & 63, k = idx >> 6;
        float v = Wn2[k * 64 + n];
        __nv_bfloat16 hb = __float2bfloat16(v);
        ((__nv_bfloat16*)(smw + 8704))[n * 72 + k] = hb;
        ((__nv_bfloat16*)(smw + 11008))[n * 72 + k] = __float2bfloat16(v - __bfloat162float(hb));
    }
    if (tid < 64) { smf[13312 + tid] = bn1[tid]; smf[13376 + tid] = bn2[tid]; }
    __syncthreads();

    int lane = tid & 31, warp = tid >> 5;
    uint32_t* A1H = smw + ND_PW + warp * 3328;
    uint32_t* A1L = A1H + 1088;
    uint32_t* A2H = A1H + 2176;
    uint32_t* A2L = A1H + 2752;
    const int r0 = lane >> 2, q = lane & 3;
    const int le = lane >> 1, half = lane & 1;
    int nwarp = gridDim.x * 8;

    for (int t = blockIdx.x * 8 + warp; t < NN / 16; t += nwarp) {
        int node = t * 16 + le;
        const float4* ph = (const float4*)(h + (size_t)node * 64 + half * 32);
        const float4* pa = (const float4*)(g_agg + (size_t)node * 64 + half * 32);
        #pragma unroll
        for (int i = 0; i < 8; i++) {
            float4 u = ph[i];
            uint32_t h0, l0, h1, l1;
            split_pair(u.x, u.y, h0, l0);
            split_pair(u.z, u.w, h1, l1);
            int off = le * 68 + half * 16 + i * 2;
            A1H[off] = h0; A1H[off + 1] = h1;
            A1L[off] = l0; A1L[off + 1] = l1;
            float4 v = pa[i];
            split_pair(v.x, v.y, h0, l0);
            split_pair(v.z, v.w, h1, l1);
            off += 32;
            A1H[off] = h0; A1H[off + 1] = h1;
            A1L[off] = l0; A1L[off + 1] = l1;
        }
        __syncwarp();

        float acc[8][4];
        #pragma unroll
        for (int nt = 0; nt < 8; nt++)
            acc[nt][0] = acc[nt][1] = acc[nt][2] = acc[nt][3] = 0.f;
        #pragma unroll
        for (int ks = 0; ks < 8; ks++) {
            int abase = r0 * 68 + ks * 8 + q;
            uint32_t ah0 = A1H[abase],     ah1 = A1H[abase + 544];
            uint32_t ah2 = A1H[abase + 4], ah3 = A1H[abase + 548];
            uint32_t al0 = A1L[abase],     al1 = A1L[abase + 544];
            uint32_t al2 = A1L[abase + 4], al3 = A1L[abase + 548];
            #pragma unroll
            for (int nt = 0; nt < 8; nt++) {
                int bw = (nt * 8 + r0) * 68 + ks * 8 + q;
                uint32_t bh0 = smw[bw],        bh1 = smw[bw + 4];
                uint32_t bl0 = smw[4352 + bw], bl1 = smw[4352 + bw + 4];
                mma_bf16(acc[nt], ah0, ah1, ah2, ah3, bh0, bh1);
                mma_bf16(acc[nt], al0, al1, al2, al3, bh0, bh1);
                mma_bf16(acc[nt], ah0, ah1, ah2, ah3, bl0, bl1);
            }
        }
        #pragma unroll
        for (int nt = 0; nt < 8; nt++) {
            int col = nt * 8 + 2 * q;
            float b0 = smf[13312 + col], b1 = smf[13312 + col + 1];
            uint32_t hp, lp;
            split_pair(silu(acc[nt][0] + b0), silu(acc[nt][1] + b1), hp, lp);
            A2H[r0 * 36 + nt * 4 + q] = hp; A2L[r0 * 36 + nt * 4 + q] = lp;
            split_pair(silu(acc[nt][2] + b0), silu(acc[nt][3] + b1), hp, lp);
            A2H[(r0 + 8) * 36 + nt * 4 + q] = hp; A2L[(r0 + 8) * 36 + nt * 4 + q] = lp;
        }
        __syncwarp();

        #pragma unroll
        for (int nt = 0; nt < 8; nt++)
            acc[nt][0] = acc[nt][1] = acc[nt][2] = acc[nt][3] = 0.f;
        #pragma unroll
        for (int ks = 0; ks < 4; ks++) {
            int abase = r0 * 36 + ks * 8 + q;
            uint32_t ah0 = A2H[abase],     ah1 = A2H[abase + 288];
            uint32_t ah2 = A2H[abase + 4], ah3 = A2H[abase + 292];
            uint32_t al0 = A2L[abase],     al1 = A2L[abase + 288];
            uint32_t al2 = A2L[abase + 4], al3 = A2L[abase + 292];
            #pragma unroll
            for (int nt = 0; nt < 8; nt++) {
                int bw = (nt * 8 + r0) * 36 + ks * 8 + q;
                uint32_t bh0 = smw[8704 + bw],  bh1 = smw[8704 + bw + 4];
                uint32_t bl0 = smw[11008 + bw], bl1 = smw[11008 + bw + 4];
                mma_bf16(acc[nt], ah0, ah1, ah2, ah3, bh0, bh1);
                mma_bf16(acc[nt], al0, al1, al2, al3, bh0, bh1);
                mma_bf16(acc[nt], ah0, ah1, ah2, ah3, bl0, bl1);
            }
        }
        int n0 = t * 16 + r0, n1 = n0 + 8;
        #pragma unroll
        for (int nt = 0; nt < 8; nt++) {
            int col = nt * 8 + 2 * q;
            float b0 = smf[13376 + col], b1 = smf[13376 + col + 1];
            ((float2*)hout)[(size_t)n0 * 32 + nt * 4 + q] = make_float2(acc[nt][0] + b0, acc[nt][1] + b1);
            ((float2*)hout)[(size_t)n1 * 32 + nt * 4 + q] = make_float2(acc[nt][2] + b0, acc[nt][3] + b1);
        }
        if (lane < 16) {
            int n = t * 16 + lane;
            float cnt = (float)g_hist[n];
            cnt = cnt > 1.f ? cnt : 1.f;
            float inv = 1.f / cnt;
            cout[n * 3 + 0] = coord[n * 3 + 0] + g_aggc[n * 3 + 0] * inv;
            cout[n * 3 + 1] = coord[n * 3 + 1] + g_aggc[n * 3 + 1] * inv;
            cout[n * 3 + 2] = coord[n * 3 + 2] + g_aggc[n * 3 + 2] * inv;
        }
        __syncwarp();
    }
}

extern "C" void kernel_launch(void* const* d_in, const int* in_sizes, int n_in,
                              void* d_out, int out_size)
{
    const float* h     = (const float*)d_in[0];
    const float* coord = (const float*)d_in[1];
    const void*  ei    = d_in[2];
    const float* emask = (const float*)d_in[3];
    const float* We1 = (const float*)d_in[4];  const float* be1 = (const float*)d_in[5];
    const float* We2 = (const float*)d_in[6];  const float* be2 = (const float*)d_in[7];
    const float* Wn1 = (const float*)d_in[8];  const float* bn1 = (const float*)d_in[9];
    const float* Wn2 = (const float*)d_in[10]; const float* bn2 = (const float*)d_in[11];
    const float* Wc1 = (const float*)d_in[12]; const float* bc1 = (const float*)d_in[13];
    const float* Wc2 = (const float*)d_in[14];

    float* hout = (float*)d_out;
    float* cout = hout + (size_t)NN * 64;

    cudaFuncSetAttribute(hprep_kernel, cudaFuncAttributeMaxDynamicSharedMemorySize, HP_SMEM_BYTES);
    cudaFuncSetAttribute(edge_kernel, cudaFuncAttributeMaxDynamicSharedMemorySize, SM_EDGE_BYTES);
    cudaFuncSetAttribute(node_kernel, cudaFuncAttributeMaxDynamicSharedMemorySize, ND_SMEM_BYTES);

    zero_kernel<<<2048, 256>>>((const int*)ei);
    hist_kernel<<<1184, 256>>>(ei);
    scan_kernel<<<1, 1024>>>();
    scatter_kernel<<<1184, 256>>>(ei);
    hprep_kernel<<<296, 256, HP_SMEM_BYTES>>>(h, We1, be1);
    edge_kernel<<<148, 512, SM_EDGE_BYTES>>>(coord, ei, emask, We1, We2, be2, Wc1, bc1, Wc2);
    node_kernel<<<148, 256, ND_SMEM_BYTES>>>(h, coord, Wn1, bn1, Wn2, bn2, hout, cout);
}

// round 15
// speedup vs baseline: 1.6526x; 1.3822x over previous
#include <cuda_runtime.h>
#include <cuda_bf16.h>
#include <cstdint>

#define NN 40000
#define EE 1280000
#define WTILES (EE / 16)

// ---------------- scratch (allocation-free) ----------------
__device__ float g_agg[NN * 64];
__device__ float g_aggc[NN * 3];
__device__ float g_H1[NN * 64];   // h @ We1[0:64]  + be1
__device__ float g_H2[NN * 64];   // h @ We1[64:128]
__device__ int   g_hist[NN];      // edges per row (== cnt)
__device__ int   g_start[NN];
__device__ int   g_cursor[NN];
__device__ int   g_sorted[EE];    // edge ids sorted by row
__device__ int   g_idx64;

// fast, accurate silu: 2 MUFU (ex2.approx + rcp.approx), rel err ~1e-6
__device__ __forceinline__ float fsilu(float v) {
    float e, r;
    asm("ex2.approx.f32 %0, %1;" : "=f"(e) : "f"(-1.44269504f * v));
    asm("rcp.approx.f32 %0, %1;" : "=f"(r) : "f"(1.0f + e));
    return v * r;
}
// 1-MUFU silu for the coord head only (result scaled by Wc2 ~ 3e-4)
__device__ __forceinline__ float tsilu(float v) {
    float t;
    asm("tanh.approx.f32 %0, %1;" : "=f"(t) : "f"(0.5f * v));
    return v * (0.5f * t + 0.5f);
}

__device__ __forceinline__ uint32_t pack_bf16x2(float lo_elem, float hi_elem) {
    uint32_t r;
    asm("cvt.rn.bf16x2.f32 %0, %1, %2;" : "=r"(r) : "f"(hi_elem), "f"(lo_elem));
    return r;
}
__device__ __forceinline__ void split_pair(float x, float y, uint32_t& hi, uint32_t& lo) {
    hi = pack_bf16x2(x, y);
    __nv_bfloat162 t;
    *reinterpret_cast<uint32_t*>(&t) = hi;
    lo = pack_bf16x2(x - __low2float(t), y - __high2float(t));
}

__device__ __forceinline__ void mma_bf16(float acc[4], uint32_t a0, uint32_t a1,
                                         uint32_t a2, uint32_t a3, uint32_t b0, uint32_t b1) {
    asm volatile(
        "mma.sync.aligned.m16n8k16.row.col.f32.bf16.bf16.f32 "
        "{%0,%1,%2,%3}, {%4,%5,%6,%7}, {%8,%9}, {%0,%1,%2,%3};"
        : "+f"(acc[0]), "+f"(acc[1]), "+f"(acc[2]), "+f"(acc[3])
        : "r"(a0), "r"(a1), "r"(a2), "r"(a3), "r"(b0), "r"(b1));
}

__device__ __forceinline__ int edge_row(const void* ei_raw, int e, int is64) {
    return is64 ? (int)((const long long*)ei_raw)[e] : ((const int*)ei_raw)[e];
}
__device__ __forceinline__ int edge_col(const void* ei_raw, int e, int is64) {
    return is64 ? (int)((const long long*)ei_raw)[EE + e] : ((const int*)ei_raw)[EE + e];
}

// ---------------- zero + dtype detect ----------------
__global__ void zero_kernel(const int* __restrict__ ei32) {
    int i = blockIdx.x * blockDim.x + threadIdx.x;
    int stride = gridDim.x * blockDim.x;
    for (int k = i; k < NN * 64; k += stride) g_agg[k] = 0.f;
    for (int k = i; k < NN * 3;  k += stride) g_aggc[k] = 0.f;
    for (int k = i; k < NN;      k += stride) g_hist[k] = 0;
    if (i == 0) {
        int all_zero = 1;
        #pragma unroll
        for (int k = 1; k < 64; k += 2) all_zero &= (ei32[k] == 0);
        g_idx64 = all_zero;
    }
}

// ---------------- counting sort ----------------
__global__ void hist_kernel(const void* __restrict__ ei_raw) {
    int is64 = g_idx64;
    int i = blockIdx.x * blockDim.x + threadIdx.x;
    int stride = gridDim.x * blockDim.x;
    for (int e = i; e < EE; e += stride)
        atomicAdd(&g_hist[edge_row(ei_raw, e, is64)], 1);
}

__global__ void scan_kernel() {
    __shared__ int ssum[1024];
    int t = threadIdx.x;
    int base = t * 40;
    int loc[40];
    int s = 0;
    #pragma unroll
    for (int i = 0; i < 40; i++) {
        int idx = base + i;
        int v = (idx < NN) ? g_hist[idx] : 0;
        loc[i] = s;
        s += v;
    }
    ssum[t] = s;
    __syncthreads();
    for (int off = 1; off < 1024; off <<= 1) {
        int v = (t >= off) ? ssum[t - off] : 0;
        __syncthreads();
        ssum[t] += v;
        __syncthreads();
    }
    int excl = ssum[t] - s;
    #pragma unroll
    for (int i = 0; i < 40; i++) {
        int idx = base + i;
        if (idx < NN) { g_start[idx] = excl + loc[i]; g_cursor[idx] = excl + loc[i]; }
    }
}

__global__ void scatter_kernel(const void* __restrict__ ei_raw) {
    int is64 = g_idx64;
    int i = blockIdx.x * blockDim.x + threadIdx.x;
    int stride = gridDim.x * blockDim.x;
    for (int e = i; e < EE; e += stride) {
        int r = edge_row(ei_raw, e, is64);
        int pos = atomicAdd(&g_cursor[r], 1);
        g_sorted[pos] = e;
    }
}

// ---------------- hprep: H1 = h@We1_top + be1, H2 = h@We1_bot (HMMA, 3-term) ----------------
#define HP_SMEM_BYTES ((9280 + 8 * 1152) * 4)

__global__ void __launch_bounds__(256, 2)
hprep_kernel(const float* __restrict__ h, const float* __restrict__ We1,
             const float* __restrict__ be1)
{
    extern __shared__ uint32_t smw[];
    float* smf = (float*)smw;
    int tid = threadIdx.x;
    for (int idx = tid; idx < 8192; idx += 256) {
        int n = idx & 127, k = idx >> 7;
        float v = We1[(k + ((n >= 64) ? 64 : 0)) * 64 + (n & 63)];
        __nv_bfloat16 hb = __float2bfloat16(v);
        ((__nv_bfloat16*)(smw))[n * 72 + k] = hb;
        ((__nv_bfloat16*)(smw + 4608))[n * 72 + k] = __float2bfloat16(v - __bfloat162float(hb));
    }
    if (tid < 64) smf[9216 + tid] = be1[tid];
    __syncthreads();

    int lane = tid & 31, warp = tid >> 5;
    uint32_t* AH = smw + 9280 + warp * 1152;
    uint32_t* AL = AH + 576;
    const int r0 = lane >> 2, q = lane & 3;
    const int le = lane >> 1, half = lane & 1;
    int nwarp = gridDim.x * 8;

    for (int t = blockIdx.x * 8 + warp; t < NN / 16; t += nwarp) {
        int node = t * 16 + le;
        const float4* p = (const float4*)(h + (size_t)node * 64 + half * 32);
        float4 u[8];
        #pragma unroll
        for (int i = 0; i < 8; i++) u[i] = p[i];
        #pragma unroll
        for (int i = 0; i < 8; i++) {
            uint32_t h0, l0, h1, l1;
            split_pair(u[i].x, u[i].y, h0, l0);
            split_pair(u[i].z, u[i].w, h1, l1);
            int off = le * 36 + half * 16 + i * 2;
            AH[off] = h0; AH[off + 1] = h1;
            AL[off] = l0; AL[off + 1] = l1;
        }
        __syncwarp();

        float acc[16][4];
        #pragma unroll
        for (int nt = 0; nt < 16; nt++)
            acc[nt][0] = acc[nt][1] = acc[nt][2] = acc[nt][3] = 0.f;
        #pragma unroll
        for (int ks = 0; ks < 4; ks++) {
            int abase = r0 * 36 + ks * 8 + q;
            uint32_t ah0 = AH[abase],     ah1 = AH[abase + 288];
            uint32_t ah2 = AH[abase + 4], ah3 = AH[abase + 292];
            uint32_t al0 = AL[abase],     al1 = AL[abase + 288];
            uint32_t al2 = AL[abase + 4], al3 = AL[abase + 292];
            #pragma unroll
            for (int nt = 0; nt < 16; nt++) {
                int bw = (nt * 8 + r0) * 36 + ks * 8 + q;
                uint32_t bh0 = smw[bw],        bh1 = smw[bw + 4];
                uint32_t bl0 = smw[4608 + bw], bl1 = smw[4608 + bw + 4];
                mma_bf16(acc[nt], ah0, ah1, ah2, ah3, bh0, bh1);
                mma_bf16(acc[nt], al0, al1, al2, al3, bh0, bh1);
                mma_bf16(acc[nt], ah0, ah1, ah2, ah3, bl0, bl1);
            }
        }
        int n0 = t * 16 + r0, n1 = n0 + 8;
        #pragma unroll
        for (int nt = 0; nt < 8; nt++) {
            int col = nt * 8 + 2 * q;
            float b0 = smf[9216 + col], b1 = smf[9216 + col + 1];
            ((float2*)g_H1)[(size_t)n0 * 32 + nt * 4 + q] = make_float2(acc[nt][0] + b0, acc[nt][1] + b1);
            ((float2*)g_H1)[(size_t)n1 * 32 + nt * 4 + q] = make_float2(acc[nt][2] + b0, acc[nt][3] + b1);
        }
        #pragma unroll
        for (int nt = 8; nt < 16; nt++) {
            int w = (nt - 8) * 4 + q;
            ((float2*)g_H2)[(size_t)n0 * 32 + w] = make_float2(acc[nt][0], acc[nt][1]);
            ((float2*)g_H2)[(size_t)n1 * 32 + w] = make_float2(acc[nt][2], acc[nt][3]);
        }
        __syncwarp();
    }
}

// ---------------- edge mega-kernel: sorted edges, HMMA, segmented reduce ----------------
#define RSTR 36
#define W2H_OFF 0
#define W2L_OFF 2304
#define WCH_OFF 4608
#define BE2_OFF 6912
#define BC1_OFF 6976
#define WC2_OFF 7040
#define W128_OFF 7104
#define PW_OFF  7168
#define PW_SIZE 1232
#define SM_EDGE_BYTES ((PW_OFF + 16 * PW_SIZE) * 4)   // 107520

__global__ void __launch_bounds__(512, 1)
edge_kernel(const float* __restrict__ coord,
            const void* __restrict__ ei_raw, const float* __restrict__ emask,
            const float* __restrict__ We1, const float* __restrict__ We2,
            const float* __restrict__ be2, const float* __restrict__ Wc1,
            const float* __restrict__ bc1, const float* __restrict__ Wc2)
{
    extern __shared__ uint32_t smw[];
    float* smf = (float*)smw;
    int tid = threadIdx.x;

    for (int idx = tid; idx < 4096; idx += 512) {
        int n = idx & 63, k = idx >> 6;
        float v = We2[k * 64 + n];
        __nv_bfloat16 hb = __float2bfloat16(v);
        ((__nv_bfloat16*)(smw + W2H_OFF))[n * 72 + k] = hb;
        ((__nv_bfloat16*)(smw + W2L_OFF))[n * 72 + k] = __float2bfloat16(v - __bfloat162float(hb));
        ((__nv_bfloat16*)(smw + WCH_OFF))[n * 72 + k] = __float2bfloat16(Wc1[k * 64 + n]);
    }
    if (tid < 64) {
        smf[BE2_OFF + tid]  = be2[tid];
        smf[BC1_OFF + tid]  = bc1[tid];
        smf[WC2_OFF + tid]  = Wc2[tid];
        smf[W128_OFF + tid] = We1[128 * 64 + tid];
    }
    __syncthreads();

    const int is64 = g_idx64;

    int lane = tid & 31, warp = tid >> 5;
    uint32_t* pw   = smw + PW_OFF + warp * PW_SIZE;
    uint32_t* A2H  = pw;
    uint32_t* A2L  = pw + 576;
    float*    Mf   = (float*)pw;          // overlaps A2 (A2 dead when M written)
    float*    sMSK = (float*)(pw + 1152);
    float*    sDX  = (float*)(pw + 1168);
    float*    sDY  = (float*)(pw + 1184);
    float*    sDZ  = (float*)(pw + 1200);
    int*      sRI  = (int*)(pw + 1216);

    const float* be2s = smf + BE2_OFF;
    const float* bc1s = smf + BC1_OFF;
    const float* wc2s = smf + WC2_OFF;
    const float* w128 = smf + W128_OFF;

    const int r0 = lane >> 2, q = lane & 3;
    const int le = lane >> 1, half = lane & 1;

    for (int g = blockIdx.x * 16 + warp; g < WTILES; g += 148 * 16) {
        int e = g_sorted[g * 16 + le];
        int ri = edge_row(ei_raw, e, is64);
        int ci = edge_col(ei_raw, e, is64);
        float msk = emask[e];
        float dx = coord[ri * 3 + 0] - coord[ci * 3 + 0];
        float dy = coord[ri * 3 + 1] - coord[ci * 3 + 1];
        float dz = coord[ri * 3 + 2] - coord[ci * 3 + 2];
        float radial = dx * dx + dy * dy + dz * dz;
        if (!half) { sMSK[le] = msk; sDX[le] = dx; sDY[le] = dy; sDZ[le] = dz; sRI[le] = ri; }

        // ---- gather (hoisted loads, full MLP) + exact layer-1 + silu + split -> A2 ----
        const float4* p1 = (const float4*)(g_H1 + (size_t)ri * 64 + half * 32);
        const float4* p2 = (const float4*)(g_H2 + (size_t)ci * 64 + half * 32);
        float4 u[8], v[8];
        #pragma unroll
        for (int i = 0; i < 8; i++) u[i] = p1[i];
        #pragma unroll
        for (int i = 0; i < 8; i++) v[i] = p2[i];
        #pragma unroll
        for (int i = 0; i < 8; i++) {
            int cb = half * 32 + i * 4;
            float x0 = fsilu(u[i].x + v[i].x + radial * w128[cb + 0]);
            float x1 = fsilu(u[i].y + v[i].y + radial * w128[cb + 1]);
            float x2 = fsilu(u[i].z + v[i].z + radial * w128[cb + 2]);
            float x3 = fsilu(u[i].w + v[i].w + radial * w128[cb + 3]);
            uint32_t h0, l0, h1, l1;
            split_pair(x0, x1, h0, l0);
            split_pair(x2, x3, h1, l1);
            int off = le * RSTR + half * 16 + i * 2;
            A2H[off] = h0; A2H[off + 1] = h1;
            A2L[off] = l0; A2L[off + 1] = l1;
        }
        __syncwarp();

        // ---- GEMM2: [16x64] = A2 (3-term bf16) x W2^T ----
        float acc[8][4];
        #pragma unroll
        for (int nt = 0; nt < 8; nt++)
            acc[nt][0] = acc[nt][1] = acc[nt][2] = acc[nt][3] = 0.f;
        #pragma unroll
        for (int ks = 0; ks < 4; ks++) {
            int abase = r0 * RSTR + ks * 8 + q;
            uint32_t ah0 = A2H[abase],     ah1 = A2H[abase + 8 * RSTR];
            uint32_t ah2 = A2H[abase + 4], ah3 = A2H[abase + 8 * RSTR + 4];
            uint32_t al0 = A2L[abase],     al1 = A2L[abase + 8 * RSTR];
            uint32_t al2 = A2L[abase + 4], al3 = A2L[abase + 8 * RSTR + 4];
            #pragma unroll
            for (int nt = 0; nt < 8; nt++) {
                int bw = (nt * 8 + r0) * RSTR + ks * 8 + q;
                uint32_t bh0 = smw[W2H_OFF + bw], bh1 = smw[W2H_OFF + bw + 4];
                uint32_t bl0 = smw[W2L_OFF + bw], bl1 = smw[W2L_OFF + bw + 4];
                mma_bf16(acc[nt], ah0, ah1, ah2, ah3, bh0, bh1);
                mma_bf16(acc[nt], al0, al1, al2, al3, bh0, bh1);
                mma_bf16(acc[nt], ah0, ah1, ah2, ah3, bl0, bl1);
            }
        }
        __syncwarp();   // A2 reads done; M may now overwrite the region

        // ---- epilogue2: m = silu(+be2)*mask -> M(smem f32) + af(registers for GEMM3) ----
        float mk0 = sMSK[r0], mk1 = sMSK[r0 + 8];
        uint32_t af[8][2];
        #pragma unroll
        for (int nt = 0; nt < 8; nt++) {
            int col = nt * 8 + 2 * q;
            float m00 = fsilu(acc[nt][0] + be2s[col])     * mk0;
            float m01 = fsilu(acc[nt][1] + be2s[col + 1]) * mk0;
            float m10 = fsilu(acc[nt][2] + be2s[col])     * mk1;
            float m11 = fsilu(acc[nt][3] + be2s[col + 1]) * mk1;
            af[nt][0] = pack_bf16x2(m00, m01);
            af[nt][1] = pack_bf16x2(m10, m11);
            *(float2*)&Mf[r0 * 68 + col]       = make_float2(m00, m01);
            *(float2*)&Mf[(r0 + 8) * 68 + col] = make_float2(m10, m11);
        }
        __syncwarp();

        // ---- segmented reduction over sorted rows: lane owns cols 2*lane..+1 ----
        {
            float2 sacc = make_float2(0.f, 0.f);
            int cur = sRI[0];
            #pragma unroll
            for (int i = 0; i < 16; i++) {
                float2 v2 = *(const float2*)&Mf[i * 68 + 2 * lane];
                sacc.x += v2.x; sacc.y += v2.y;
                int nxt = (i < 15) ? sRI[i + 1] : -1;
                if (nxt != cur) {
                    asm volatile("red.global.add.v2.f32 [%0], {%1, %2};"
                                 :: "l"(&g_agg[(size_t)cur * 64 + 2 * lane]),
                                    "f"(sacc.x), "f"(sacc.y) : "memory");
                    sacc.x = 0.f; sacc.y = 0.f;
                    cur = nxt;
                }
            }
        }

        // ---- GEMM3: [16x64] = m (registers, 1-term bf16) x Wc1^T ----
        #pragma unroll
        for (int nt = 0; nt < 8; nt++)
            acc[nt][0] = acc[nt][1] = acc[nt][2] = acc[nt][3] = 0.f;
        #pragma unroll
        for (int ks = 0; ks < 4; ks++) {
            uint32_t a0 = af[2 * ks][0],     a1 = af[2 * ks][1];
            uint32_t a2 = af[2 * ks + 1][0], a3 = af[2 * ks + 1][1];
            #pragma unroll
            for (int nt = 0; nt < 8; nt++) {
                int bw = (nt * 8 + r0) * RSTR + ks * 8 + q;
                mma_bf16(acc[nt], a0, a1, a2, a3, smw[WCH_OFF + bw], smw[WCH_OFF + bw + 4]);
            }
        }

        // ---- epilogue3: c = silu(+bc1)@Wc2; coord atomics ----
        float s0 = 0.f, s1 = 0.f;
        #pragma unroll
        for (int nt = 0; nt < 8; nt++) {
            int col = nt * 8 + 2 * q;
            s0 += tsilu(acc[nt][0] + bc1s[col]) * wc2s[col]
                + tsilu(acc[nt][1] + bc1s[col + 1]) * wc2s[col + 1];
            s1 += tsilu(acc[nt][2] + bc1s[col]) * wc2s[col]
                + tsilu(acc[nt][3] + bc1s[col + 1]) * wc2s[col + 1];
        }
        s0 += __shfl_xor_sync(0xffffffffu, s0, 1);
        s0 += __shfl_xor_sync(0xffffffffu, s0, 2);
        s1 += __shfl_xor_sync(0xffffffffu, s1, 1);
        s1 += __shfl_xor_sync(0xffffffffu, s1, 2);
        if (q == 0) {
            int rn0 = sRI[r0], rn1 = sRI[r0 + 8];
            float cc0 = s0 * mk0;
            atomicAdd(&g_aggc[(size_t)rn0 * 3 + 0], sDX[r0] * cc0);
            atomicAdd(&g_aggc[(size_t)rn0 * 3 + 1], sDY[r0] * cc0);
            atomicAdd(&g_aggc[(size_t)rn0 * 3 + 2], sDZ[r0] * cc0);
            float cc1 = s1 * mk1;
            atomicAdd(&g_aggc[(size_t)rn1 * 3 + 0], sDX[r0 + 8] * cc1);
            atomicAdd(&g_aggc[(size_t)rn1 * 3 + 1], sDY[r0 + 8] * cc1);
            atomicAdd(&g_aggc[(size_t)rn1 * 3 + 2], sDZ[r0 + 8] * cc1);
        }
        __syncwarp();
    }
}

// ---------------- node kernel (HMMA, 3-term both GEMMs) ----------------
#define ND_PW 13440
#define ND_SMEM_BYTES ((ND_PW + 8 * 3328) * 4)

__global__ void __launch_bounds__(256, 1)
node_kernel(const float* __restrict__ h, const float* __restrict__ coord,
            const float* __restrict__ Wn1, const float* __restrict__ bn1,
            const float* __restrict__ Wn2, const float* __restrict__ bn2,
            float* __restrict__ hout, float* __restrict__ cout)
{
    extern __shared__ uint32_t smw[];
    float* smf = (float*)smw;
    int tid = threadIdx.x;

    for (int idx = tid; idx < 8192; idx += 256) {
        int n = idx & 63, k = idx >> 6;
        float v = Wn1[k * 64 + n];
        __nv_bfloat16 hb = __float2bfloat16(v);
        ((__nv_bfloat16*)(smw))[n * 136 + k] = hb;
        ((__nv_bfloat16*)(smw + 4352))[n * 136 + k] = __float2bfloat16(v - __bfloat162float(hb));
    }
    for (int idx = tid; idx < 4096; idx += 256) {
        int n = idx & 63, k = idx >> 6;
        float v = Wn2[k * 64 + n];
        __nv_bfloat16 hb = __float2bfloat16(v);
        ((__nv_bfloat16*)(smw + 8704))[n * 72 + k] = hb;
        ((__nv_bfloat16*)(smw + 11008))[n * 72 + k] = __float2bfloat16(v - __bfloat162float(hb));
    }
    if (tid < 64) { smf[13312 + tid] = bn1[tid]; smf[13376 + tid] = bn2[tid]; }
    __syncthreads();

    int lane = tid & 31, warp = tid >> 5;
    uint32_t* A1H = smw + ND_PW + warp * 3328;
    uint32_t* A1L = A1H + 1088;
    uint32_t* A2H = A1H + 2176;
    uint32_t* A2L = A1H + 2752;
    const int r0 = lane >> 2, q = lane & 3;
    const int le = lane >> 1, half = lane & 1;
    int nwarp = gridDim.x * 8;

    for (int t = blockIdx.x * 8 + warp; t < NN / 16; t += nwarp) {
        int node = t * 16 + le;
        const float4* ph = (const float4*)(h + (size_t)node * 64 + half * 32);
        const float4* pa = (const float4*)(g_agg + (size_t)node * 64 + half * 32);
        float4 u[8], v[8];
        #pragma unroll
        for (int i = 0; i < 8; i++) u[i] = ph[i];
        #pragma unroll
        for (int i = 0; i < 8; i++) v[i] = pa[i];
        #pragma unroll
        for (int i = 0; i < 8; i++) {
            uint32_t h0, l0, h1, l1;
            split_pair(u[i].x, u[i].y, h0, l0);
            split_pair(u[i].z, u[i].w, h1, l1);
            int off = le * 68 + half * 16 + i * 2;
            A1H[off] = h0; A1H[off + 1] = h1;
            A1L[off] = l0; A1L[off + 1] = l1;
            split_pair(v[i].x, v[i].y, h0, l0);
            split_pair(v[i].z, v[i].w, h1, l1);
            off += 32;
            A1H[off] = h0; A1H[off + 1] = h1;
            A1L[off] = l0; A1L[off + 1] = l1;
        }
        __syncwarp();

        float acc[8][4];
        #pragma unroll
        for (int nt = 0; nt < 8; nt++)
            acc[nt][0] = acc[nt][1] = acc[nt][2] = acc[nt][3] = 0.f;
        #pragma unroll
        for (int ks = 0; ks < 8; ks++) {
            int abase = r0 * 68 + ks * 8 + q;
            uint32_t ah0 = A1H[abase],     ah1 = A1H[abase + 544];
            uint32_t ah2 = A1H[abase + 4], ah3 = A1H[abase + 548];
            uint32_t al0 = A1L[abase],     al1 = A1L[abase + 544];
            uint32_t al2 = A1L[abase + 4], al3 = A1L[abase + 548];
            #pragma unroll
            for (int nt = 0; nt < 8; nt++) {
                int bw = (nt * 8 + r0) * 68 + ks * 8 + q;
                uint32_t bh0 = smw[bw],        bh1 = smw[bw + 4];
                uint32_t bl0 = smw[4352 + bw], bl1 = smw[4352 + bw + 4];
                mma_bf16(acc[nt], ah0, ah1, ah2, ah3, bh0, bh1);
                mma_bf16(acc[nt], al0, al1, al2, al3, bh0, bh1);
                mma_bf16(acc[nt], ah0, ah1, ah2, ah3, bl0, bl1);
            }
        }
        #pragma unroll
        for (int nt = 0; nt < 8; nt++) {
            int col = nt * 8 + 2 * q;
            float b0 = smf[13312 + col], b1 = smf[13312 + col + 1];
            uint32_t hp, lp;
            split_pair(fsilu(acc[nt][0] + b0), fsilu(acc[nt][1] + b1), hp, lp);
            A2H[r0 * 36 + nt * 4 + q] = hp; A2L[r0 * 36 + nt * 4 + q] = lp;
            split_pair(fsilu(acc[nt][2] + b0), fsilu(acc[nt][3] + b1), hp, lp);
            A2H[(r0 + 8) * 36 + nt * 4 + q] = hp; A2L[(r0 + 8) * 36 + nt * 4 + q] = lp;
        }
        __syncwarp();

        #pragma unroll
        for (int nt = 0; nt < 8; nt++)
            acc[nt][0] = acc[nt][1] = acc[nt][2] = acc[nt][3] = 0.f;
        #pragma unroll
        for (int ks = 0; ks < 4; ks++) {
            int abase = r0 * 36 + ks * 8 + q;
            uint32_t ah0 = A2H[abase],     ah1 = A2H[abase + 288];
            uint32_t ah2 = A2H[abase + 4], ah3 = A2H[abase + 292];
            uint32_t al0 = A2L[abase],     al1 = A2L[abase + 288];
            uint32_t al2 = A2L[abase + 4], al3 = A2L[abase + 292];
            #pragma unroll
            for (int nt = 0; nt < 8; nt++) {
                int bw = (nt * 8 + r0) * 36 + ks * 8 + q;
                uint32_t bh0 = smw[8704 + bw],  bh1 = smw[8704 + bw + 4];
                uint32_t bl0 = smw[11008 + bw], bl1 = smw[11008 + bw + 4];
                mma_bf16(acc[nt], ah0, ah1, ah2, ah3, bh0, bh1);
                mma_bf16(acc[nt], al0, al1, al2, al3, bh0, bh1);
                mma_bf16(acc[nt], ah0, ah1, ah2, ah3, bl0, bl1);
            }
        }
        int n0 = t * 16 + r0, n1 = n0 + 8;
        #pragma unroll
        for (int nt = 0; nt < 8; nt++) {
            int col = nt * 8 + 2 * q;
            float b0 = smf[13376 + col], b1 = smf[13376 + col + 1];
            ((float2*)hout)[(size_t)n0 * 32 + nt * 4 + q] = make_float2(acc[nt][0] + b0, acc[nt][1] + b1);
            ((float2*)hout)[(size_t)n1 * 32 + nt * 4 + q] = make_float2(acc[nt][2] + b0, acc[nt][3] + b1);
        }
        if (lane < 16) {
            int n = t * 16 + lane;
            float cnt = (float)g_hist[n];
            cnt = cnt > 1.f ? cnt : 1.f;
            float inv;
            asm("rcp.approx.f32 %0, %1;" : "=f"(inv) : "f"(cnt));
            cout[n * 3 + 0] = coord[n * 3 + 0] + g_aggc[n * 3 + 0] * inv;
            cout[n * 3 + 1] = coord[n * 3 + 1] + g_aggc[n * 3 + 1] * inv;
            cout[n * 3 + 2] = coord[n * 3 + 2] + g_aggc[n * 3 + 2] * inv;
        }
        __syncwarp();
    }
}

extern "C" void kernel_launch(void* const* d_in, const int* in_sizes, int n_in,
                              void* d_out, int out_size)
{
    const float* h     = (const float*)d_in[0];
    const float* coord = (const float*)d_in[1];
    const void*  ei    = d_in[2];
    const float* emask = (const float*)d_in[3];
    const float* We1 = (const float*)d_in[4];  const float* be1 = (const float*)d_in[5];
    const float* We2 = (const float*)d_in[6];  const float* be2 = (const float*)d_in[7];
    const float* Wn1 = (const float*)d_in[8];  const float* bn1 = (const float*)d_in[9];
    const float* Wn2 = (const float*)d_in[10]; const float* bn2 = (const float*)d_in[11];
    const float* Wc1 = (const float*)d_in[12]; const float* bc1 = (const float*)d_in[13];
    const float* Wc2 = (const float*)d_in[14];

    float* hout = (float*)d_out;
    float* cout = hout + (size_t)NN * 64;

    cudaFuncSetAttribute(hprep_kernel, cudaFuncAttributeMaxDynamicSharedMemorySize, HP_SMEM_BYTES);
    cudaFuncSetAttribute(edge_kernel, cudaFuncAttributeMaxDynamicSharedMemorySize, SM_EDGE_BYTES);
    cudaFuncSetAttribute(node_kernel, cudaFuncAttributeMaxDynamicSharedMemorySize, ND_SMEM_BYTES);

    zero_kernel<<<2048, 256>>>((const int*)ei);
    hist_kernel<<<1184, 256>>>(ei);
    scan_kernel<<<1, 1024>>>();
    scatter_kernel<<<1184, 256>>>(ei);
    hprep_kernel<<<296, 256, HP_SMEM_BYTES>>>(h, We1, be1);
    edge_kernel<<<148, 512, SM_EDGE_BYTES>>>(coord, ei, emask, We1, We2, be2, Wc1, bc1, Wc2);
    node_kernel<<<148, 256, ND_SMEM_BYTES>>>(h, coord, Wn1, bn1, Wn2, bn2, hout, cout);
}

// round 16
// speedup vs baseline: 1.6632x; 1.0064x over previous
#include <cuda_runtime.h>
#include <cuda_bf16.h>
#include <cstdint>

#define NN 40000
#define EE 1280000
#define WTILES (EE / 16)

// ---------------- scratch (allocation-free) ----------------
__device__ float g_agg[NN * 64];
__device__ float g_aggc[NN * 3];
__device__ float g_H1[NN * 64];   // h @ We1[0:64]  + be1
__device__ float g_H2[NN * 64];   // h @ We1[64:128]
__device__ int   g_hist[NN];      // edges per row (== cnt)
__device__ int   g_cursor[NN];    // scatter cursors
__device__ float4 g_eA[EE];       // {dx, dy, dz, msk} sorted by row
__device__ int2   g_eB[EE];       // {ri, ci} sorted by row
__device__ int   g_idx64;

// fast, accurate silu: 2 MUFU (ex2.approx + rcp.approx), rel err ~1e-6
__device__ __forceinline__ float fsilu(float v) {
    float e, r;
    asm("ex2.approx.f32 %0, %1;" : "=f"(e) : "f"(-1.44269504f * v));
    asm("rcp.approx.f32 %0, %1;" : "=f"(r) : "f"(1.0f + e));
    return v * r;
}
// 1-MUFU silu for the coord head only (result scaled by Wc2 ~ 3e-4)
__device__ __forceinline__ float tsilu(float v) {
    float t;
    asm("tanh.approx.f32 %0, %1;" : "=f"(t) : "f"(0.5f * v));
    return v * (0.5f * t + 0.5f);
}

__device__ __forceinline__ uint32_t pack_bf16x2(float lo_elem, float hi_elem) {
    uint32_t r;
    asm("cvt.rn.bf16x2.f32 %0, %1, %2;" : "=r"(r) : "f"(hi_elem), "f"(lo_elem));
    return r;
}
__device__ __forceinline__ void split_pair(float x, float y, uint32_t& hi, uint32_t& lo) {
    hi = pack_bf16x2(x, y);
    __nv_bfloat162 t;
    *reinterpret_cast<uint32_t*>(&t) = hi;
    lo = pack_bf16x2(x - __low2float(t), y - __high2float(t));
}

__device__ __forceinline__ void mma_bf16(float acc[4], uint32_t a0, uint32_t a1,
                                         uint32_t a2, uint32_t a3, uint32_t b0, uint32_t b1) {
    asm volatile(
        "mma.sync.aligned.m16n8k16.row.col.f32.bf16.bf16.f32 "
        "{%0,%1,%2,%3}, {%4,%5,%6,%7}, {%8,%9}, {%0,%1,%2,%3};"
        : "+f"(acc[0]), "+f"(acc[1]), "+f"(acc[2]), "+f"(acc[3])
        : "r"(a0), "r"(a1), "r"(a2), "r"(a3), "r"(b0), "r"(b1));
}

__device__ __forceinline__ int edge_row(const void* ei_raw, int e, int is64) {
    return is64 ? (int)((const long long*)ei_raw)[e] : ((const int*)ei_raw)[e];
}
__device__ __forceinline__ int edge_col(const void* ei_raw, int e, int is64) {
    return is64 ? (int)((const long long*)ei_raw)[EE + e] : ((const int*)ei_raw)[EE + e];
}

// ---------------- zero + dtype detect ----------------
__global__ void zero_kernel(const int* __restrict__ ei32) {
    int i = blockIdx.x * blockDim.x + threadIdx.x;
    int stride = gridDim.x * blockDim.x;
    for (int k = i; k < NN * 64; k += stride) g_agg[k] = 0.f;
    for (int k = i; k < NN * 3;  k += stride) g_aggc[k] = 0.f;
    for (int k = i; k < NN;      k += stride) g_hist[k] = 0;
    if (i == 0) {
        int all_zero = 1;
        #pragma unroll
        for (int k = 1; k < 64; k += 2) all_zero &= (ei32[k] == 0);
        g_idx64 = all_zero;
    }
}

// ---------------- counting sort: histogram (4 edges/thread, vector loads) ----------------
__global__ void hist_kernel(const void* __restrict__ ei_raw) {
    int is64 = g_idx64;
    int i = blockIdx.x * blockDim.x + threadIdx.x;
    int stride = gridDim.x * blockDim.x;
    if (is64) {
        const longlong2* p = (const longlong2*)ei_raw;
        for (int b = i; b < EE / 4; b += stride) {
            longlong2 a = p[2 * b], c = p[2 * b + 1];
            atomicAdd(&g_hist[(int)a.x], 1);
            atomicAdd(&g_hist[(int)a.y], 1);
            atomicAdd(&g_hist[(int)c.x], 1);
            atomicAdd(&g_hist[(int)c.y], 1);
        }
    } else {
        const int4* p = (const int4*)ei_raw;
        for (int b = i; b < EE / 4; b += stride) {
            int4 a = p[b];
            atomicAdd(&g_hist[a.x], 1);
            atomicAdd(&g_hist[a.y], 1);
            atomicAdd(&g_hist[a.z], 1);
            atomicAdd(&g_hist[a.w], 1);
        }
    }
}

// one block, 1024 threads: exclusive scan of g_hist -> g_cursor
__global__ void scan_kernel() {
    __shared__ int ssum[1024];
    int t = threadIdx.x;
    int base = t * 40;
    int loc[40];
    int s = 0;
    #pragma unroll
    for (int i = 0; i < 40; i++) {
        int idx = base + i;
        int v = (idx < NN) ? g_hist[idx] : 0;
        loc[i] = s;
        s += v;
    }
    ssum[t] = s;
    __syncthreads();
    for (int off = 1; off < 1024; off <<= 1) {
        int v = (t >= off) ? ssum[t - off] : 0;
        __syncthreads();
        ssum[t] += v;
        __syncthreads();
    }
    int excl = ssum[t] - s;
    #pragma unroll
    for (int i = 0; i < 40; i++) {
        int idx = base + i;
        if (idx < NN) g_cursor[idx] = excl + loc[i];
    }
}

// ---------------- fused scatter + hprep ----------------
// blocks [0, HP_BLOCKS): hprep (HMMA);  blocks [HP_BLOCKS, ...): scatter w/ coord pre-gather
#define HP_BLOCKS 296
#define SC_BLOCKS 888
#define HP_SMEM_BYTES ((9280 + 8 * 1152) * 4)

__global__ void __launch_bounds__(256)
scatter_hprep_kernel(const void* __restrict__ ei_raw, const float* __restrict__ emask,
                     const float* __restrict__ coord,
                     const float* __restrict__ h, const float* __restrict__ We1,
                     const float* __restrict__ be1)
{
    extern __shared__ uint32_t smw[];
    int tid = threadIdx.x;

    if (blockIdx.x >= HP_BLOCKS) {
        // ---------------- scatter role ----------------
        int is64 = g_idx64;
        int i = (blockIdx.x - HP_BLOCKS) * 256 + tid;
        int stride = SC_BLOCKS * 256;
        for (int e = i; e < EE; e += stride) {
            int r = edge_row(ei_raw, e, is64);
            int c = edge_col(ei_raw, e, is64);
            float msk = emask[e];
            float dx = coord[r * 3 + 0] - coord[c * 3 + 0];
            float dy = coord[r * 3 + 1] - coord[c * 3 + 1];
            float dz = coord[r * 3 + 2] - coord[c * 3 + 2];
            int pos = atomicAdd(&g_cursor[r], 1);
            g_eA[pos] = make_float4(dx, dy, dz, msk);
            g_eB[pos] = make_int2(r, c);
        }
        return;
    }

    // ---------------- hprep role (HMMA, 3-term) ----------------
    float* smf = (float*)smw;
    for (int idx = tid; idx < 8192; idx += 256) {
        int n = idx & 127, k = idx >> 7;
        float v = We1[(k + ((n >= 64) ? 64 : 0)) * 64 + (n & 63)];
        __nv_bfloat16 hb = __float2bfloat16(v);
        ((__nv_bfloat16*)(smw))[n * 72 + k] = hb;
        ((__nv_bfloat16*)(smw + 4608))[n * 72 + k] = __float2bfloat16(v - __bfloat162float(hb));
    }
    if (tid < 64) smf[9216 + tid] = be1[tid];
    __syncthreads();

    int lane = tid & 31, warp = tid >> 5;
    uint32_t* AH = smw + 9280 + warp * 1152;
    uint32_t* AL = AH + 576;
    const int r0 = lane >> 2, q = lane & 3;
    const int le = lane >> 1, half = lane & 1;
    int nwarp = HP_BLOCKS * 8;

    for (int t = blockIdx.x * 8 + warp; t < NN / 16; t += nwarp) {
        int node = t * 16 + le;
        const float4* p = (const float4*)(h + (size_t)node * 64 + half * 32);
        float4 u[8];
        #pragma unroll
        for (int i = 0; i < 8; i++) u[i] = p[i];
        #pragma unroll
        for (int i = 0; i < 8; i++) {
            uint32_t h0, l0, h1, l1;
            split_pair(u[i].x, u[i].y, h0, l0);
            split_pair(u[i].z, u[i].w, h1, l1);
            int off = le * 36 + half * 16 + i * 2;
            AH[off] = h0; AH[off + 1] = h1;
            AL[off] = l0; AL[off + 1] = l1;
        }
        __syncwarp();

        float acc[16][4];
        #pragma unroll
        for (int nt = 0; nt < 16; nt++)
            acc[nt][0] = acc[nt][1] = acc[nt][2] = acc[nt][3] = 0.f;
        #pragma unroll
        for (int ks = 0; ks < 4; ks++) {
            int abase = r0 * 36 + ks * 8 + q;
            uint32_t ah0 = AH[abase],     ah1 = AH[abase + 288];
            uint32_t ah2 = AH[abase + 4], ah3 = AH[abase + 292];
            uint32_t al0 = AL[abase],     al1 = AL[abase + 288];
            uint32_t al2 = AL[abase + 4], al3 = AL[abase + 292];
            #pragma unroll
            for (int nt = 0; nt < 16; nt++) {
                int bw = (nt * 8 + r0) * 36 + ks * 8 + q;
                uint32_t bh0 = smw[bw],        bh1 = smw[bw + 4];
                uint32_t bl0 = smw[4608 + bw], bl1 = smw[4608 + bw + 4];
                mma_bf16(acc[nt], ah0, ah1, ah2, ah3, bh0, bh1);
                mma_bf16(acc[nt], al0, al1, al2, al3, bh0, bh1);
                mma_bf16(acc[nt], ah0, ah1, ah2, ah3, bl0, bl1);
            }
        }
        int n0 = t * 16 + r0, n1 = n0 + 8;
        #pragma unroll
        for (int nt = 0; nt < 8; nt++) {
            int col = nt * 8 + 2 * q;
            float b0 = smf[9216 + col], b1 = smf[9216 + col + 1];
            ((float2*)g_H1)[(size_t)n0 * 32 + nt * 4 + q] = make_float2(acc[nt][0] + b0, acc[nt][1] + b1);
            ((float2*)g_H1)[(size_t)n1 * 32 + nt * 4 + q] = make_float2(acc[nt][2] + b0, acc[nt][3] + b1);
        }
        #pragma unroll
        for (int nt = 8; nt < 16; nt++) {
            int w = (nt - 8) * 4 + q;
            ((float2*)g_H2)[(size_t)n0 * 32 + w] = make_float2(acc[nt][0], acc[nt][1]);
            ((float2*)g_H2)[(size_t)n1 * 32 + w] = make_float2(acc[nt][2], acc[nt][3]);
        }
        __syncwarp();
    }
}

// ---------------- edge mega-kernel: packed sorted edges, HMMA, segmented reduce ----------------
#define RSTR 36
#define W2H_OFF 0
#define W2L_OFF 2304
#define WCH_OFF 4608
#define BE2_OFF 6912
#define BC1_OFF 6976
#define WC2_OFF 7040
#define W128_OFF 7104
#define PW_OFF  7168
#define PW_SIZE 1232
#define SM_EDGE_BYTES ((PW_OFF + 16 * PW_SIZE) * 4)   // 107520

__global__ void __launch_bounds__(512, 1)
edge_kernel(const float* __restrict__ We1, const float* __restrict__ We2,
            const float* __restrict__ be2, const float* __restrict__ Wc1,
            const float* __restrict__ bc1, const float* __restrict__ Wc2)
{
    extern __shared__ uint32_t smw[];
    float* smf = (float*)smw;
    int tid = threadIdx.x;

    for (int idx = tid; idx < 4096; idx += 512) {
        int n = idx & 63, k = idx >> 6;
        float v = We2[k * 64 + n];
        __nv_bfloat16 hb = __float2bfloat16(v);
        ((__nv_bfloat16*)(smw + W2H_OFF))[n * 72 + k] = hb;
        ((__nv_bfloat16*)(smw + W2L_OFF))[n * 72 + k] = __float2bfloat16(v - __bfloat162float(hb));
        ((__nv_bfloat16*)(smw + WCH_OFF))[n * 72 + k] = __float2bfloat16(Wc1[k * 64 + n]);
    }
    if (tid < 64) {
        smf[BE2_OFF + tid]  = be2[tid];
        smf[BC1_OFF + tid]  = bc1[tid];
        smf[WC2_OFF + tid]  = Wc2[tid];
        smf[W128_OFF + tid] = We1[128 * 64 + tid];
    }
    __syncthreads();

    int lane = tid & 31, warp = tid >> 5;
    uint32_t* pw   = smw + PW_OFF + warp * PW_SIZE;
    uint32_t* A2H  = pw;
    uint32_t* A2L  = pw + 576;
    float*    Mf   = (float*)pw;          // overlaps A2 (A2 dead when M written)
    float*    sMSK = (float*)(pw + 1152);
    float*    sDX  = (float*)(pw + 1168);
    float*    sDY  = (float*)(pw + 1184);
    float*    sDZ  = (float*)(pw + 1200);
    int*      sRI  = (int*)(pw + 1216);

    const float* be2s = smf + BE2_OFF;
    const float* bc1s = smf + BC1_OFF;
    const float* wc2s = smf + WC2_OFF;
    const float* w128 = smf + W128_OFF;

    const int r0 = lane >> 2, q = lane & 3;
    const int le = lane >> 1, half = lane & 1;

    for (int g = blockIdx.x * 16 + warp; g < WTILES; g += 148 * 16) {
        int p = g * 16 + le;
        float4 eA = g_eA[p];
        int2   eB = g_eB[p];
        float dx = eA.x, dy = eA.y, dz = eA.z, msk = eA.w;
        int ri = eB.x, ci = eB.y;
        float radial = dx * dx + dy * dy + dz * dz;
        if (!half) { sMSK[le] = msk; sDX[le] = dx; sDY[le] = dy; sDZ[le] = dz; sRI[le] = ri; }

        // ---- gather (hoisted loads, full MLP) + exact layer-1 + silu + split -> A2 ----
        const float4* p1 = (const float4*)(g_H1 + (size_t)ri * 64 + half * 32);
        const float4* p2 = (const float4*)(g_H2 + (size_t)ci * 64 + half * 32);
        float4 u[8], v[8];
        #pragma unroll
        for (int i = 0; i < 8; i++) u[i] = p1[i];
        #pragma unroll
        for (int i = 0; i < 8; i++) v[i] = p2[i];
        #pragma unroll
        for (int i = 0; i < 8; i++) {
            int cb = half * 32 + i * 4;
            float x0 = fsilu(u[i].x + v[i].x + radial * w128[cb + 0]);
            float x1 = fsilu(u[i].y + v[i].y + radial * w128[cb + 1]);
            float x2 = fsilu(u[i].z + v[i].z + radial * w128[cb + 2]);
            float x3 = fsilu(u[i].w + v[i].w + radial * w128[cb + 3]);
            uint32_t h0, l0, h1, l1;
            split_pair(x0, x1, h0, l0);
            split_pair(x2, x3, h1, l1);
            int off = le * RSTR + half * 16 + i * 2;
            A2H[off] = h0; A2H[off + 1] = h1;
            A2L[off] = l0; A2L[off + 1] = l1;
        }
        __syncwarp();

        // ---- GEMM2: [16x64] = A2 (3-term bf16) x W2^T ----
        float acc[8][4];
        #pragma unroll
        for (int nt = 0; nt < 8; nt++)
            acc[nt][0] = acc[nt][1] = acc[nt][2] = acc[nt][3] = 0.f;
        #pragma unroll
        for (int ks = 0; ks < 4; ks++) {
            int abase = r0 * RSTR + ks * 8 + q;
            uint32_t ah0 = A2H[abase],     ah1 = A2H[abase + 8 * RSTR];
            uint32_t ah2 = A2H[abase + 4], ah3 = A2H[abase + 8 * RSTR + 4];
            uint32_t al0 = A2L[abase],     al1 = A2L[abase + 8 * RSTR];
            uint32_t al2 = A2L[abase + 4], al3 = A2L[abase + 8 * RSTR + 4];
            #pragma unroll
            for (int nt = 0; nt < 8; nt++) {
                int bw = (nt * 8 + r0) * RSTR + ks * 8 + q;
                uint32_t bh0 = smw[W2H_OFF + bw], bh1 = smw[W2H_OFF + bw + 4];
                uint32_t bl0 = smw[W2L_OFF + bw], bl1 = smw[W2L_OFF + bw + 4];
                mma_bf16(acc[nt], ah0, ah1, ah2, ah3, bh0, bh1);
                mma_bf16(acc[nt], al0, al1, al2, al3, bh0, bh1);
                mma_bf16(acc[nt], ah0, ah1, ah2, ah3, bl0, bl1);
            }
        }
        __syncwarp();   // A2 reads done; M may now overwrite the region

        // ---- epilogue2: m = silu(+be2)*mask -> M(smem f32) + af(registers for GEMM3) ----
        float mk0 = sMSK[r0], mk1 = sMSK[r0 + 8];
        uint32_t af[8][2];
        #pragma unroll
        for (int nt = 0; nt < 8; nt++) {
            int col = nt * 8 + 2 * q;
            float m00 = fsilu(acc[nt][0] + be2s[col])     * mk0;
            float m01 = fsilu(acc[nt][1] + be2s[col + 1]) * mk0;
            float m10 = fsilu(acc[nt][2] + be2s[col])     * mk1;
            float m11 = fsilu(acc[nt][3] + be2s[col + 1]) * mk1;
            af[nt][0] = pack_bf16x2(m00, m01);
            af[nt][1] = pack_bf16x2(m10, m11);
            *(float2*)&Mf[r0 * 68 + col]       = make_float2(m00, m01);
            *(float2*)&Mf[(r0 + 8) * 68 + col] = make_float2(m10, m11);
        }
        __syncwarp();

        // ---- segmented reduction over sorted rows: lane owns cols 2*lane..+1 ----
        {
            float2 sacc = make_float2(0.f, 0.f);
            int cur = sRI[0];
            #pragma unroll
            for (int i = 0; i < 16; i++) {
                float2 v2 = *(const float2*)&Mf[i * 68 + 2 * lane];
                sacc.x += v2.x; sacc.y += v2.y;
                int nxt = (i < 15) ? sRI[i + 1] : -1;
                if (nxt != cur) {
                    asm volatile("red.global.add.v2.f32 [%0], {%1, %2};"
                                 :: "l"(&g_agg[(size_t)cur * 64 + 2 * lane]),
                                    "f"(sacc.x), "f"(sacc.y) : "memory");
                    sacc.x = 0.f; sacc.y = 0.f;
                    cur = nxt;
                }
            }
        }

        // ---- GEMM3: [16x64] = m (registers, 1-term bf16) x Wc1^T ----
        #pragma unroll
        for (int nt = 0; nt < 8; nt++)
            acc[nt][0] = acc[nt][1] = acc[nt][2] = acc[nt][3] = 0.f;
        #pragma unroll
        for (int ks = 0; ks < 4; ks++) {
            uint32_t a0 = af[2 * ks][0],     a1 = af[2 * ks][1];
            uint32_t a2 = af[2 * ks + 1][0], a3 = af[2 * ks + 1][1];
            #pragma unroll
            for (int nt = 0; nt < 8; nt++) {
                int bw = (nt * 8 + r0) * RSTR + ks * 8 + q;
                mma_bf16(acc[nt], a0, a1, a2, a3, smw[WCH_OFF + bw], smw[WCH_OFF + bw + 4]);
            }
        }

        // ---- epilogue3: c = silu(+bc1)@Wc2; coord atomics ----
        float s0 = 0.f, s1 = 0.f;
        #pragma unroll
        for (int nt = 0; nt < 8; nt++) {
            int col = nt * 8 + 2 * q;
            s0 += tsilu(acc[nt][0] + bc1s[col]) * wc2s[col]
                + tsilu(acc[nt][1] + bc1s[col + 1]) * wc2s[col + 1];
            s1 += tsilu(acc[nt][2] + bc1s[col]) * wc2s[col]
                + tsilu(acc[nt][3] + bc1s[col + 1]) * wc2s[col + 1];
        }
        s0 += __shfl_xor_sync(0xffffffffu, s0, 1);
        s0 += __shfl_xor_sync(0xffffffffu, s0, 2);
        s1 += __shfl_xor_sync(0xffffffffu, s1, 1);
        s1 += __shfl_xor_sync(0xffffffffu, s1, 2);
        if (q == 0) {
            int rn0 = sRI[r0], rn1 = sRI[r0 + 8];
            float cc0 = s0 * mk0;
            atomicAdd(&g_aggc[(size_t)rn0 * 3 + 0], sDX[r0] * cc0);
            atomicAdd(&g_aggc[(size_t)rn0 * 3 + 1], sDY[r0] * cc0);
            atomicAdd(&g_aggc[(size_t)rn0 * 3 + 2], sDZ[r0] * cc0);
            float cc1 = s1 * mk1;
            atomicAdd(&g_aggc[(size_t)rn1 * 3 + 0], sDX[r0 + 8] * cc1);
            atomicAdd(&g_aggc[(size_t)rn1 * 3 + 1], sDY[r0 + 8] * cc1);
            atomicAdd(&g_aggc[(size_t)rn1 * 3 + 2], sDZ[r0 + 8] * cc1);
        }
        __syncwarp();
    }
}

// ---------------- node kernel (HMMA, 3-term both GEMMs) ----------------
#define ND_PW 13440
#define ND_SMEM_BYTES ((ND_PW + 8 * 3328) * 4)

__global__ void __launch_bounds__(256, 1)
node_kernel(const float* __restrict__ h, const float* __restrict__ coord,
            const float* __restrict__ Wn1, const float* __restrict__ bn1,
            const float* __restrict__ Wn2, const float* __restrict__ bn2,
            float* __restrict__ hout, float* __restrict__ cout)
{
    extern __shared__ uint32_t smw[];
    float* smf = (float*)smw;
    int tid = threadIdx.x;

    for (int idx = tid; idx < 8192; idx += 256) {
        int n = idx & 63, k = idx >> 6;
        float v = Wn1[k * 64 + n];
        __nv_bfloat16 hb = __float2bfloat16(v);
        ((__nv_bfloat16*)(smw))[n * 136 + k] = hb;
        ((__nv_bfloat16*)(smw + 4352))[n * 136 + k] = __float2bfloat16(v - __bfloat162float(hb));
    }
    for (int idx = tid; idx < 4096; idx += 256) {
        int n = idx & 63, k = idx >> 6;
        float v = Wn2[k * 64 + n];
        __nv_bfloat16 hb = __float2bfloat16(v);
        ((__nv_bfloat16*)(smw + 8704))[n * 72 + k] = hb;
        ((__nv_bfloat16*)(smw + 11008))[n * 72 + k] = __float2bfloat16(v - __bfloat162float(hb));
    }
    if (tid < 64) { smf[13312 + tid] = bn1[tid]; smf[13376 + tid] = bn2[tid]; }
    __syncthreads();

    int lane = tid & 31, warp = tid >> 5;
    uint32_t* A1H = smw + ND_PW + warp * 3328;
    uint32_t* A1L = A1H + 1088;
    uint32_t* A2H = A1H + 2176;
    uint32_t* A2L = A1H + 2752;
    const int r0 = lane >> 2, q = lane & 3;
    const int le = lane >> 1, half = lane & 1;
    int nwarp = gridDim.x * 8;

    for (int t = blockIdx.x * 8 + warp; t < NN / 16; t += nwarp) {
        int node = t * 16 + le;
        const float4* ph = (const float4*)(h + (size_t)node * 64 + half * 32);
        const float4* pa = (const float4*)(g_agg + (size_t)node * 64 + half * 32);
        float4 u[8], v[8];
        #pragma unroll
        for (int i = 0; i < 8; i++) u[i] = ph[i];
        #pragma unroll
        for (int i = 0; i < 8; i++) v[i] = pa[i];
        #pragma unroll
        for (int i = 0; i < 8; i++) {
            uint32_t h0, l0, h1, l1;
            split_pair(u[i].x, u[i].y, h0, l0);
            split_pair(u[i].z, u[i].w, h1, l1);
            int off = le * 68 + half * 16 + i * 2;
            A1H[off] = h0; A1H[off + 1] = h1;
            A1L[off] = l0; A1L[off + 1] = l1;
            split_pair(v[i].x, v[i].y, h0, l0);
            split_pair(v[i].z, v[i].w, h1, l1);
            off += 32;
            A1H[off] = h0; A1H[off + 1] = h1;
            A1L[off] = l0; A1L[off + 1] = l1;
        }
        __syncwarp();

        float acc[8][4];
        #pragma unroll
        for (int nt = 0; nt < 8; nt++)
            acc[nt][0] = acc[nt][1] = acc[nt][2] = acc[nt][3] = 0.f;
        #pragma unroll
        for (int ks = 0; ks < 8; ks++) {
            int abase = r0 * 68 + ks * 8 + q;
            uint32_t ah0 = A1H[abase],     ah1 = A1H[abase + 544];
            uint32_t ah2 = A1H[abase + 4], ah3 = A1H[abase + 548];
            uint32_t al0 = A1L[abase],     al1 = A1L[abase + 544];
            uint32_t al2 = A1L[abase + 4], al3 = A1L[abase + 548];
            #pragma unroll
            for (int nt = 0; nt < 8; nt++) {
                int bw = (nt * 8 + r0) * 68 + ks * 8 + q;
                uint32_t bh0 = smw[bw],        bh1 = smw[bw + 4];
                uint32_t bl0 = smw[4352 + bw], bl1 = smw[4352 + bw + 4];
                mma_bf16(acc[nt], ah0, ah1, ah2, ah3, bh0, bh1);
                mma_bf16(acc[nt], al0, al1, al2, al3, bh0, bh1);
                mma_bf16(acc[nt], ah0, ah1, ah2, ah3, bl0, bl1);
            }
        }
        #pragma unroll
        for (int nt = 0; nt < 8; nt++) {
            int col = nt * 8 + 2 * q;
            float b0 = smf[13312 + col], b1 = smf[13312 + col + 1];
            uint32_t hp, lp;
            split_pair(fsilu(acc[nt][0] + b0), fsilu(acc[nt][1] + b1), hp, lp);
            A2H[r0 * 36 + nt * 4 + q] = hp; A2L[r0 * 36 + nt * 4 + q] = lp;
            split_pair(fsilu(acc[nt][2] + b0), fsilu(acc[nt][3] + b1), hp, lp);
            A2H[(r0 + 8) * 36 + nt * 4 + q] = hp; A2L[(r0 + 8) * 36 + nt * 4 + q] = lp;
        }
        __syncwarp();

        #pragma unroll
        for (int nt = 0; nt < 8; nt++)
            acc[nt][0] = acc[nt][1] = acc[nt][2] = acc[nt][3] = 0.f;
        #pragma unroll
        for (int ks = 0; ks < 4; ks++) {
            int abase = r0 * 36 + ks * 8 + q;
            uint32_t ah0 = A2H[abase],     ah1 = A2H[abase + 288];
            uint32_t ah2 = A2H[abase + 4], ah3 = A2H[abase + 292];
            uint32_t al0 = A2L[abase],     al1 = A2L[abase + 288];
            uint32_t al2 = A2L[abase + 4], al3 = A2L[abase + 292];
            #pragma unroll
            for (int nt = 0; nt < 8; nt++) {
                int bw = (nt * 8 + r0) * 36 + ks * 8 + q;
                uint32_t bh0 = smw[8704 + bw],  bh1 = smw[8704 + bw + 4];
                uint32_t bl0 = smw[11008 + bw], bl1 = smw[11008 + bw + 4];
                mma_bf16(acc[nt], ah0, ah1, ah2, ah3, bh0, bh1);
                mma_bf16(acc[nt], al0, al1, al2, al3, bh0, bh1);
                mma_bf16(acc[nt], ah0, ah1, ah2, ah3, bl0, bl1);
            }
        }
        int n0 = t * 16 + r0, n1 = n0 + 8;
        #pragma unroll
        for (int nt = 0; nt < 8; nt++) {
            int col = nt * 8 + 2 * q;
            float b0 = smf[13376 + col], b1 = smf[13376 + col + 1];
            ((float2*)hout)[(size_t)n0 * 32 + nt * 4 + q] = make_float2(acc[nt][0] + b0, acc[nt][1] + b1);
            ((float2*)hout)[(size_t)n1 * 32 + nt * 4 + q] = make_float2(acc[nt][2] + b0, acc[nt][3] + b1);
        }
        if (lane < 16) {
            int n = t * 16 + lane;
            float cnt = (float)g_hist[n];
            cnt = cnt > 1.f ? cnt : 1.f;
            float inv;
            asm("rcp.approx.f32 %0, %1;" : "=f"(inv) : "f"(cnt));
            cout[n * 3 + 0] = coord[n * 3 + 0] + g_aggc[n * 3 + 0] * inv;
            cout[n * 3 + 1] = coord[n * 3 + 1] + g_aggc[n * 3 + 1] * inv;
            cout[n * 3 + 2] = coord[n * 3 + 2] + g_aggc[n * 3 + 2] * inv;
        }
        __syncwarp();
    }
}

extern "C" void kernel_launch(void* const* d_in, const int* in_sizes, int n_in,
                              void* d_out, int out_size)
{
    const float* h     = (const float*)d_in[0];
    const float* coord = (const float*)d_in[1];
    const void*  ei    = d_in[2];
    const float* emask = (const float*)d_in[3];
    const float* We1 = (const float*)d_in[4];  const float* be1 = (const float*)d_in[5];
    const float* We2 = (const float*)d_in[6];  const float* be2 = (const float*)d_in[7];
    const float* Wn1 = (const float*)d_in[8];  const float* bn1 = (const float*)d_in[9];
    const float* Wn2 = (const float*)d_in[10]; const float* bn2 = (const float*)d_in[11];
    const float* Wc1 = (const float*)d_in[12]; const float* bc1 = (const float*)d_in[13];
    const float* Wc2 = (const float*)d_in[14];

    float* hout = (float*)d_out;
    float* cout = hout + (size_t)NN * 64;

    cudaFuncSetAttribute(scatter_hprep_kernel, cudaFuncAttributeMaxDynamicSharedMemorySize, HP_SMEM_BYTES);
    cudaFuncSetAttribute(edge_kernel, cudaFuncAttributeMaxDynamicSharedMemorySize, SM_EDGE_BYTES);
    cudaFuncSetAttribute(node_kernel, cudaFuncAttributeMaxDynamicSharedMemorySize, ND_SMEM_BYTES);

    zero_kernel<<<2048, 256>>>((const int*)ei);
    hist_kernel<<<1250, 256>>>(ei);
    scan_kernel<<<1, 1024>>>();
    scatter_hprep_kernel<<<HP_BLOCKS + SC_BLOCKS, 256, HP_SMEM_BYTES>>>(ei, emask, coord, h, We1, be1);
    edge_kernel<<<148, 512, SM_EDGE_BYTES>>>(We1, We2, be2, Wc1, bc1, Wc2);
    node_kernel<<<148, 256, ND_SMEM_BYTES>>>(h, coord, Wn1, bn1, Wn2, bn2, hout, cout);
}

// round 17
// speedup vs baseline: 1.7286x; 1.0393x over previous
#include <cuda_runtime.h>
#include <cuda_bf16.h>
#include <cstdint>

#define NN 40000
#define EE 1280000
#define WTILES (EE / 16)

// ---------------- scratch (allocation-free) ----------------
__device__ float g_agg[NN * 64];
__device__ float g_aggc[NN * 3];
__device__ float g_H1[NN * 64];   // h @ We1[0:64]  + be1
__device__ float g_H2[NN * 64];   // h @ We1[64:128]
__device__ int   g_hist[NN];      // edges per row (== cnt)
__device__ int   g_cursor[NN];    // scatter cursors
__device__ float4 g_eA[EE];       // {dx, dy, dz, msk} sorted by row
__device__ int2   g_eB[EE];       // {ri, ci} sorted by row
__device__ int   g_idx64;

// fast, accurate silu: 2 MUFU (ex2.approx + rcp.approx), rel err ~1e-6
__device__ __forceinline__ float fsilu(float v) {
    float e, r;
    asm("ex2.approx.f32 %0, %1;" : "=f"(e) : "f"(-1.44269504f * v));
    asm("rcp.approx.f32 %0, %1;" : "=f"(r) : "f"(1.0f + e));
    return v * r;
}
// 1-MUFU silu via tanh.approx: abs err ~2^-11, used on the throughput-critical edge path
__device__ __forceinline__ float tsilu(float v) {
    float t;
    asm("tanh.approx.f32 %0, %1;" : "=f"(t) : "f"(0.5f * v));
    return v * (0.5f * t + 0.5f);
}

__device__ __forceinline__ uint32_t pack_bf16x2(float lo_elem, float hi_elem) {
    uint32_t r;
    asm("cvt.rn.bf16x2.f32 %0, %1, %2;" : "=r"(r) : "f"(hi_elem), "f"(lo_elem));
    return r;
}
__device__ __forceinline__ void split_pair(float x, float y, uint32_t& hi, uint32_t& lo) {
    hi = pack_bf16x2(x, y);
    __nv_bfloat162 t;
    *reinterpret_cast<uint32_t*>(&t) = hi;
    lo = pack_bf16x2(x - __low2float(t), y - __high2float(t));
}

__device__ __forceinline__ void mma_bf16(float acc[4], uint32_t a0, uint32_t a1,
                                         uint32_t a2, uint32_t a3, uint32_t b0, uint32_t b1) {
    asm volatile(
        "mma.sync.aligned.m16n8k16.row.col.f32.bf16.bf16.f32 "
        "{%0,%1,%2,%3}, {%4,%5,%6,%7}, {%8,%9}, {%0,%1,%2,%3};"
        : "+f"(acc[0]), "+f"(acc[1]), "+f"(acc[2]), "+f"(acc[3])
        : "r"(a0), "r"(a1), "r"(a2), "r"(a3), "r"(b0), "r"(b1));
}

__device__ __forceinline__ int edge_row(const void* ei_raw, int e, int is64) {
    return is64 ? (int)((const long long*)ei_raw)[e] : ((const int*)ei_raw)[e];
}
__device__ __forceinline__ int edge_col(const void* ei_raw, int e, int is64) {
    return is64 ? (int)((const long long*)ei_raw)[EE + e] : ((const int*)ei_raw)[EE + e];
}

// ---------------- zero + dtype detect ----------------
__global__ void zero_kernel(const int* __restrict__ ei32) {
    int i = blockIdx.x * blockDim.x + threadIdx.x;
    int stride = gridDim.x * blockDim.x;
    for (int k = i; k < NN * 64; k += stride) g_agg[k] = 0.f;
    for (int k = i; k < NN * 3;  k += stride) g_aggc[k] = 0.f;
    for (int k = i; k < NN;      k += stride) g_hist[k] = 0;
    if (i == 0) {
        int all_zero = 1;
        #pragma unroll
        for (int k = 1; k < 64; k += 2) all_zero &= (ei32[k] == 0);
        g_idx64 = all_zero;
    }
}

// ---------------- counting sort: histogram (4 edges/thread, vector loads) ----------------
__global__ void hist_kernel(const void* __restrict__ ei_raw) {
    int is64 = g_idx64;
    int i = blockIdx.x * blockDim.x + threadIdx.x;
    int stride = gridDim.x * blockDim.x;
    if (is64) {
        const longlong2* p = (const longlong2*)ei_raw;
        for (int b = i; b < EE / 4; b += stride) {
            longlong2 a = p[2 * b], c = p[2 * b + 1];
            atomicAdd(&g_hist[(int)a.x], 1);
            atomicAdd(&g_hist[(int)a.y], 1);
            atomicAdd(&g_hist[(int)c.x], 1);
            atomicAdd(&g_hist[(int)c.y], 1);
        }
    } else {
        const int4* p = (const int4*)ei_raw;
        for (int b = i; b < EE / 4; b += stride) {
            int4 a = p[b];
            atomicAdd(&g_hist[a.x], 1);
            atomicAdd(&g_hist[a.y], 1);
            atomicAdd(&g_hist[a.z], 1);
            atomicAdd(&g_hist[a.w], 1);
        }
    }
}

// one block, 1024 threads: exclusive scan of g_hist -> g_cursor
__global__ void scan_kernel() {
    __shared__ int ssum[1024];
    int t = threadIdx.x;
    int base = t * 40;
    int loc[40];
    int s = 0;
    #pragma unroll
    for (int i = 0; i < 40; i++) {
        int idx = base + i;
        int v = (idx < NN) ? g_hist[idx] : 0;
        loc[i] = s;
        s += v;
    }
    ssum[t] = s;
    __syncthreads();
    for (int off = 1; off < 1024; off <<= 1) {
        int v = (t >= off) ? ssum[t - off] : 0;
        __syncthreads();
        ssum[t] += v;
        __syncthreads();
    }
    int excl = ssum[t] - s;
    #pragma unroll
    for (int i = 0; i < 40; i++) {
        int idx = base + i;
        if (idx < NN) g_cursor[idx] = excl + loc[i];
    }
}

// ---------------- fused scatter + hprep ----------------
#define HP_BLOCKS 296
#define SC_BLOCKS 888
#define HP_SMEM_BYTES ((9280 + 8 * 1152) * 4)

__global__ void __launch_bounds__(256)
scatter_hprep_kernel(const void* __restrict__ ei_raw, const float* __restrict__ emask,
                     const float* __restrict__ coord,
                     const float* __restrict__ h, const float* __restrict__ We1,
                     const float* __restrict__ be1)
{
    extern __shared__ uint32_t smw[];
    int tid = threadIdx.x;

    if (blockIdx.x >= HP_BLOCKS) {
        // ---------------- scatter role ----------------
        int is64 = g_idx64;
        int i = (blockIdx.x - HP_BLOCKS) * 256 + tid;
        int stride = SC_BLOCKS * 256;
        for (int e = i; e < EE; e += stride) {
            int r = edge_row(ei_raw, e, is64);
            int c = edge_col(ei_raw, e, is64);
            float msk = emask[e];
            float dx = coord[r * 3 + 0] - coord[c * 3 + 0];
            float dy = coord[r * 3 + 1] - coord[c * 3 + 1];
            float dz = coord[r * 3 + 2] - coord[c * 3 + 2];
            int pos = atomicAdd(&g_cursor[r], 1);
            g_eA[pos] = make_float4(dx, dy, dz, msk);
            g_eB[pos] = make_int2(r, c);
        }
        return;
    }

    // ---------------- hprep role (HMMA, 3-term) ----------------
    float* smf = (float*)smw;
    for (int idx = tid; idx < 8192; idx += 256) {
        int n = idx & 127, k = idx >> 7;
        float v = We1[(k + ((n >= 64) ? 64 : 0)) * 64 + (n & 63)];
        __nv_bfloat16 hb = __float2bfloat16(v);
        ((__nv_bfloat16*)(smw))[n * 72 + k] = hb;
        ((__nv_bfloat16*)(smw + 4608))[n * 72 + k] = __float2bfloat16(v - __bfloat162float(hb));
    }
    if (tid < 64) smf[9216 + tid] = be1[tid];
    __syncthreads();

    int lane = tid & 31, warp = tid >> 5;
    uint32_t* AH = smw + 9280 + warp * 1152;
    uint32_t* AL = AH + 576;
    const int r0 = lane >> 2, q = lane & 3;
    const int le = lane >> 1, half = lane & 1;
    int nwarp = HP_BLOCKS * 8;

    for (int t = blockIdx.x * 8 + warp; t < NN / 16; t += nwarp) {
        int node = t * 16 + le;
        const float4* p = (const float4*)(h + (size_t)node * 64 + half * 32);
        float4 u[8];
        #pragma unroll
        for (int i = 0; i < 8; i++) u[i] = p[i];
        #pragma unroll
        for (int i = 0; i < 8; i++) {
            uint32_t h0, l0, h1, l1;
            split_pair(u[i].x, u[i].y, h0, l0);
            split_pair(u[i].z, u[i].w, h1, l1);
            int off = le * 36 + half * 16 + i * 2;
            AH[off] = h0; AH[off + 1] = h1;
            AL[off] = l0; AL[off + 1] = l1;
        }
        __syncwarp();

        float acc[16][4];
        #pragma unroll
        for (int nt = 0; nt < 16; nt++)
            acc[nt][0] = acc[nt][1] = acc[nt][2] = acc[nt][3] = 0.f;
        #pragma unroll
        for (int ks = 0; ks < 4; ks++) {
            int abase = r0 * 36 + ks * 8 + q;
            uint32_t ah0 = AH[abase],     ah1 = AH[abase + 288];
            uint32_t ah2 = AH[abase + 4], ah3 = AH[abase + 292];
            uint32_t al0 = AL[abase],     al1 = AL[abase + 288];
            uint32_t al2 = AL[abase + 4], al3 = AL[abase + 292];
            #pragma unroll
            for (int nt = 0; nt < 16; nt++) {
                int bw = (nt * 8 + r0) * 36 + ks * 8 + q;
                uint32_t bh0 = smw[bw],        bh1 = smw[bw + 4];
                uint32_t bl0 = smw[4608 + bw], bl1 = smw[4608 + bw + 4];
                mma_bf16(acc[nt], ah0, ah1, ah2, ah3, bh0, bh1);
                mma_bf16(acc[nt], al0, al1, al2, al3, bh0, bh1);
                mma_bf16(acc[nt], ah0, ah1, ah2, ah3, bl0, bl1);
            }
        }
        int n0 = t * 16 + r0, n1 = n0 + 8;
        #pragma unroll
        for (int nt = 0; nt < 8; nt++) {
            int col = nt * 8 + 2 * q;
            float b0 = smf[9216 + col], b1 = smf[9216 + col + 1];
            ((float2*)g_H1)[(size_t)n0 * 32 + nt * 4 + q] = make_float2(acc[nt][0] + b0, acc[nt][1] + b1);
            ((float2*)g_H1)[(size_t)n1 * 32 + nt * 4 + q] = make_float2(acc[nt][2] + b0, acc[nt][3] + b1);
        }
        #pragma unroll
        for (int nt = 8; nt < 16; nt++) {
            int w = (nt - 8) * 4 + q;
            ((float2*)g_H2)[(size_t)n0 * 32 + w] = make_float2(acc[nt][0], acc[nt][1]);
            ((float2*)g_H2)[(size_t)n1 * 32 + w] = make_float2(acc[nt][2], acc[nt][3]);
        }
        __syncwarp();
    }
}

// ---------------- edge mega-kernel: packed sorted edges, HMMA, segmented reduce ----------------
#define RSTR 36
#define W2H_OFF 0
#define W2L_OFF 2304
#define WCH_OFF 4608
#define BE2_OFF 6912
#define BC1_OFF 6976
#define WC2_OFF 7040
#define W128_OFF 7104
#define PW_OFF  7168
#define PW_SIZE 1232
#define SM_EDGE_BYTES ((PW_OFF + 16 * PW_SIZE) * 4)   // 107520

__global__ void __launch_bounds__(512, 1)
edge_kernel(const float* __restrict__ We1, const float* __restrict__ We2,
            const float* __restrict__ be2, const float* __restrict__ Wc1,
            const float* __restrict__ bc1, const float* __restrict__ Wc2)
{
    extern __shared__ uint32_t smw[];
    float* smf = (float*)smw;
    int tid = threadIdx.x;

    for (int idx = tid; idx < 4096; idx += 512) {
        int n = idx & 63, k = idx >> 6;
        float v = We2[k * 64 + n];
        __nv_bfloat16 hb = __float2bfloat16(v);
        ((__nv_bfloat16*)(smw + W2H_OFF))[n * 72 + k] = hb;
        ((__nv_bfloat16*)(smw + W2L_OFF))[n * 72 + k] = __float2bfloat16(v - __bfloat162float(hb));
        ((__nv_bfloat16*)(smw + WCH_OFF))[n * 72 + k] = __float2bfloat16(Wc1[k * 64 + n]);
    }
    if (tid < 64) {
        smf[BE2_OFF + tid]  = be2[tid];
        smf[BC1_OFF + tid]  = bc1[tid];
        smf[WC2_OFF + tid]  = Wc2[tid];
        smf[W128_OFF + tid] = We1[128 * 64 + tid];
    }
    __syncthreads();

    int lane = tid & 31, warp = tid >> 5;
    uint32_t* pw   = smw + PW_OFF + warp * PW_SIZE;
    uint32_t* A2H  = pw;
    uint32_t* A2L  = pw + 576;
    float*    Mf   = (float*)pw;          // overlaps A2 (A2 dead when M written)
    float*    sMSK = (float*)(pw + 1152);
    float*    sDX  = (float*)(pw + 1168);
    float*    sDY  = (float*)(pw + 1184);
    float*    sDZ  = (float*)(pw + 1200);
    int*      sRI  = (int*)(pw + 1216);

    const float* be2s = smf + BE2_OFF;
    const float* bc1s = smf + BC1_OFF;
    const float* wc2s = smf + WC2_OFF;
    const float* w128 = smf + W128_OFF;

    const int r0 = lane >> 2, q = lane & 3;
    const int le = lane >> 1, half = lane & 1;

    for (int g = blockIdx.x * 16 + warp; g < WTILES; g += 148 * 16) {
        int p = g * 16 + le;
        float4 eA = g_eA[p];
        int2   eB = g_eB[p];
        float dx = eA.x, dy = eA.y, dz = eA.z, msk = eA.w;
        int ri = eB.x, ci = eB.y;
        float radial = dx * dx + dy * dy + dz * dz;
        if (!half) { sMSK[le] = msk; sDX[le] = dx; sDY[le] = dy; sDZ[le] = dz; sRI[le] = ri; }

        // ---- gather (hoisted loads, full MLP) + exact layer-1 + silu(tanh) + split -> A2 ----
        const float4* p1 = (const float4*)(g_H1 + (size_t)ri * 64 + half * 32);
        const float4* p2 = (const float4*)(g_H2 + (size_t)ci * 64 + half * 32);
        float4 u[8], v[8];
        #pragma unroll
        for (int i = 0; i < 8; i++) u[i] = p1[i];
        #pragma unroll
        for (int i = 0; i < 8; i++) v[i] = p2[i];
        #pragma unroll
        for (int i = 0; i < 8; i++) {
            int cb = half * 32 + i * 4;
            float x0 = tsilu(u[i].x + v[i].x + radial * w128[cb + 0]);
            float x1 = tsilu(u[i].y + v[i].y + radial * w128[cb + 1]);
            float x2 = tsilu(u[i].z + v[i].z + radial * w128[cb + 2]);
            float x3 = tsilu(u[i].w + v[i].w + radial * w128[cb + 3]);
            uint32_t h0, l0, h1, l1;
            split_pair(x0, x1, h0, l0);
            split_pair(x2, x3, h1, l1);
            int off = le * RSTR + half * 16 + i * 2;
            A2H[off] = h0; A2H[off + 1] = h1;
            A2L[off] = l0; A2L[off + 1] = l1;
        }
        __syncwarp();

        // ---- GEMM2: [16x64] = A2 (3-term bf16) x W2^T ----
        float acc[8][4];
        #pragma unroll
        for (int nt = 0; nt < 8; nt++)
            acc[nt][0] = acc[nt][1] = acc[nt][2] = acc[nt][3] = 0.f;
        #pragma unroll
        for (int ks = 0; ks < 4; ks++) {
            int abase = r0 * RSTR + ks * 8 + q;
            uint32_t ah0 = A2H[abase],     ah1 = A2H[abase + 8 * RSTR];
            uint32_t ah2 = A2H[abase + 4], ah3 = A2H[abase + 8 * RSTR + 4];
            uint32_t al0 = A2L[abase],     al1 = A2L[abase + 8 * RSTR];
            uint32_t al2 = A2L[abase + 4], al3 = A2L[abase + 8 * RSTR + 4];
            #pragma unroll
            for (int nt = 0; nt < 8; nt++) {
                int bw = (nt * 8 + r0) * RSTR + ks * 8 + q;
                uint32_t bh0 = smw[W2H_OFF + bw], bh1 = smw[W2H_OFF + bw + 4];
                uint32_t bl0 = smw[W2L_OFF + bw], bl1 = smw[W2L_OFF + bw + 4];
                mma_bf16(acc[nt], ah0, ah1, ah2, ah3, bh0, bh1);
                mma_bf16(acc[nt], al0, al1, al2, al3, bh0, bh1);
                mma_bf16(acc[nt], ah0, ah1, ah2, ah3, bl0, bl1);
            }
        }
        __syncwarp();   // A2 reads done; M may now overwrite the region

        // ---- epilogue2: m = silu(+be2)*mask (tanh) -> M(smem f32) + af(regs for GEMM3) ----
        float mk0 = sMSK[r0], mk1 = sMSK[r0 + 8];
        uint32_t af[8][2];
        #pragma unroll
        for (int nt = 0; nt < 8; nt++) {
            int col = nt * 8 + 2 * q;
            float m00 = tsilu(acc[nt][0] + be2s[col])     * mk0;
            float m01 = tsilu(acc[nt][1] + be2s[col + 1]) * mk0;
            float m10 = tsilu(acc[nt][2] + be2s[col])     * mk1;
            float m11 = tsilu(acc[nt][3] + be2s[col + 1]) * mk1;
            af[nt][0] = pack_bf16x2(m00, m01);
            af[nt][1] = pack_bf16x2(m10, m11);
            *(float2*)&Mf[r0 * 68 + col]       = make_float2(m00, m01);
            *(float2*)&Mf[(r0 + 8) * 68 + col] = make_float2(m10, m11);
        }
        __syncwarp();

        // ---- segmented reduction over sorted rows: lane owns cols 2*lane..+1 ----
        {
            float2 sacc = make_float2(0.f, 0.f);
            int cur = sRI[0];
            #pragma unroll
            for (int i = 0; i < 16; i++) {
                float2 v2 = *(const float2*)&Mf[i * 68 + 2 * lane];
                sacc.x += v2.x; sacc.y += v2.y;
                int nxt = (i < 15) ? sRI[i + 1] : -1;
                if (nxt != cur) {
                    asm volatile("red.global.add.v2.f32 [%0], {%1, %2};"
                                 :: "l"(&g_agg[(size_t)cur * 64 + 2 * lane]),
                                    "f"(sacc.x), "f"(sacc.y) : "memory");
                    sacc.x = 0.f; sacc.y = 0.f;
                    cur = nxt;
                }
            }
        }

        // ---- GEMM3: [16x64] = m (registers, 1-term bf16) x Wc1^T ----
        #pragma unroll
        for (int nt = 0; nt < 8; nt++)
            acc[nt][0] = acc[nt][1] = acc[nt][2] = acc[nt][3] = 0.f;
        #pragma unroll
        for (int ks = 0; ks < 4; ks++) {
            uint32_t a0 = af[2 * ks][0],     a1 = af[2 * ks][1];
            uint32_t a2 = af[2 * ks + 1][0], a3 = af[2 * ks + 1][1];
            #pragma unroll
            for (int nt = 0; nt < 8; nt++) {
                int bw = (nt * 8 + r0) * RSTR + ks * 8 + q;
                mma_bf16(acc[nt], a0, a1, a2, a3, smw[WCH_OFF + bw], smw[WCH_OFF + bw + 4]);
            }
        }

        // ---- epilogue3: c = silu(+bc1)@Wc2; coord atomics ----
        float s0 = 0.f, s1 = 0.f;
        #pragma unroll
        for (int nt = 0; nt < 8; nt++) {
            int col = nt * 8 + 2 * q;
            s0 += tsilu(acc[nt][0] + bc1s[col]) * wc2s[col]
                + tsilu(acc[nt][1] + bc1s[col + 1]) * wc2s[col + 1];
            s1 += tsilu(acc[nt][2] + bc1s[col]) * wc2s[col]
                + tsilu(acc[nt][3] + bc1s[col + 1]) * wc2s[col + 1];
        }
        s0 += __shfl_xor_sync(0xffffffffu, s0, 1);
        s0 += __shfl_xor_sync(0xffffffffu, s0, 2);
        s1 += __shfl_xor_sync(0xffffffffu, s1, 1);
        s1 += __shfl_xor_sync(0xffffffffu, s1, 2);
        if (q == 0) {
            int rn0 = sRI[r0], rn1 = sRI[r0 + 8];
            float cc0 = s0 * mk0;
            atomicAdd(&g_aggc[(size_t)rn0 * 3 + 0], sDX[r0] * cc0);
            atomicAdd(&g_aggc[(size_t)rn0 * 3 + 1], sDY[r0] * cc0);
            atomicAdd(&g_aggc[(size_t)rn0 * 3 + 2], sDZ[r0] * cc0);
            float cc1 = s1 * mk1;
            atomicAdd(&g_aggc[(size_t)rn1 * 3 + 0], sDX[r0 + 8] * cc1);
            atomicAdd(&g_aggc[(size_t)rn1 * 3 + 1], sDY[r0 + 8] * cc1);
            atomicAdd(&g_aggc[(size_t)rn1 * 3 + 2], sDZ[r0 + 8] * cc1);
        }
        __syncwarp();
    }
}

// ---------------- node kernel (HMMA, 3-term both GEMMs) ----------------
#define ND_PW 13440
#define ND_SMEM_BYTES ((ND_PW + 8 * 3328) * 4)

__global__ void __launch_bounds__(256, 1)
node_kernel(const float* __restrict__ h, const float* __restrict__ coord,
            const float* __restrict__ Wn1, const float* __restrict__ bn1,
            const float* __restrict__ Wn2, const float* __restrict__ bn2,
            float* __restrict__ hout, float* __restrict__ cout)
{
    extern __shared__ uint32_t smw[];
    float* smf = (float*)smw;
    int tid = threadIdx.x;

    for (int idx = tid; idx < 8192; idx += 256) {
        int n = idx & 63, k = idx >> 6;
        float v = Wn1[k * 64 + n];
        __nv_bfloat16 hb = __float2bfloat16(v);
        ((__nv_bfloat16*)(smw))[n * 136 + k] = hb;
        ((__nv_bfloat16*)(smw + 4352))[n * 136 + k] = __float2bfloat16(v - __bfloat162float(hb));
    }
    for (int idx = tid; idx < 4096; idx += 256) {
        int n = idx & 63, k = idx >> 6;
        float v = Wn2[k * 64 + n];
        __nv_bfloat16 hb = __float2bfloat16(v);
        ((__nv_bfloat16*)(smw + 8704))[n * 72 + k] = hb;
        ((__nv_bfloat16*)(smw + 11008))[n * 72 + k] = __float2bfloat16(v - __bfloat162float(hb));
    }
    if (tid < 64) { smf[13312 + tid] = bn1[tid]; smf[13376 + tid] = bn2[tid]; }
    __syncthreads();

    int lane = tid & 31, warp = tid >> 5;
    uint32_t* A1H = smw + ND_PW + warp * 3328;
    uint32_t* A1L = A1H + 1088;
    uint32_t* A2H = A1H + 2176;
    uint32_t* A2L = A1H + 2752;
    const int r0 = lane >> 2, q = lane & 3;
    const int le = lane >> 1, half = lane & 1;
    int nwarp = gridDim.x * 8;

    for (int t = blockIdx.x * 8 + warp; t < NN / 16; t += nwarp) {
        int node = t * 16 + le;
        const float4* ph = (const float4*)(h + (size_t)node * 64 + half * 32);
        const float4* pa = (const float4*)(g_agg + (size_t)node * 64 + half * 32);
        float4 u[8], v[8];
        #pragma unroll
        for (int i = 0; i < 8; i++) u[i] = ph[i];
        #pragma unroll
        for (int i = 0; i < 8; i++) v[i] = pa[i];
        #pragma unroll
        for (int i = 0; i < 8; i++) {
            uint32_t h0, l0, h1, l1;
            split_pair(u[i].x, u[i].y, h0, l0);
            split_pair(u[i].z, u[i].w, h1, l1);
            int off = le * 68 + half * 16 + i * 2;
            A1H[off] = h0; A1H[off + 1] = h1;
            A1L[off] = l0; A1L[off + 1] = l1;
            split_pair(v[i].x, v[i].y, h0, l0);
            split_pair(v[i].z, v[i].w, h1, l1);
            off += 32;
            A1H[off] = h0; A1H[off + 1] = h1;
            A1L[off] = l0; A1L[off + 1] = l1;
        }
        __syncwarp();

        float acc[8][4];
        #pragma unroll
        for (int nt = 0; nt < 8; nt++)
            acc[nt][0] = acc[nt][1] = acc[nt][2] = acc[nt][3] = 0.f;
        #pragma unroll
        for (int ks = 0; ks < 8; ks++) {
            int abase = r0 * 68 + ks * 8 + q;
            uint32_t ah0 = A1H[abase],     ah1 = A1H[abase + 544];
            uint32_t ah2 = A1H[abase + 4], ah3 = A1H[abase + 548];
            uint32_t al0 = A1L[abase],     al1 = A1L[abase + 544];
            uint32_t al2 = A1L[abase + 4], al3 = A1L[abase + 548];
            #pragma unroll
            for (int nt = 0; nt < 8; nt++) {
                int bw = (nt * 8 + r0) * 68 + ks * 8 + q;
                uint32_t bh0 = smw[bw],        bh1 = smw[bw + 4];
                uint32_t bl0 = smw[4352 + bw], bl1 = smw[4352 + bw + 4];
                mma_bf16(acc[nt], ah0, ah1, ah2, ah3, bh0, bh1);
                mma_bf16(acc[nt], al0, al1, al2, al3, bh0, bh1);
                mma_bf16(acc[nt], ah0, ah1, ah2, ah3, bl0, bl1);
            }
        }
        #pragma unroll
        for (int nt = 0; nt < 8; nt++) {
            int col = nt * 8 + 2 * q;
            float b0 = smf[13312 + col], b1 = smf[13312 + col + 1];
            uint32_t hp, lp;
            split_pair(fsilu(acc[nt][0] + b0), fsilu(acc[nt][1] + b1), hp, lp);
            A2H[r0 * 36 + nt * 4 + q] = hp; A2L[r0 * 36 + nt * 4 + q] = lp;
            split_pair(fsilu(acc[nt][2] + b0), fsilu(acc[nt][3] + b1), hp, lp);
            A2H[(r0 + 8) * 36 + nt * 4 + q] = hp; A2L[(r0 + 8) * 36 + nt * 4 + q] = lp;
        }
        __syncwarp();

        #pragma unroll
        for (int nt = 0; nt < 8; nt++)
            acc[nt][0] = acc[nt][1] = acc[nt][2] = acc[nt][3] = 0.f;
        #pragma unroll
        for (int ks = 0; ks < 4; ks++) {
            int abase = r0 * 36 + ks * 8 + q;
            uint32_t ah0 = A2H[abase],     ah1 = A2H[abase + 288];
            uint32_t ah2 = A2H[abase + 4], ah3 = A2H[abase + 292];
            uint32_t al0 = A2L[abase],     al1 = A2L[abase + 288];
            uint32_t al2 = A2L[abase + 4], al3 = A2L[abase + 292];
            #pragma unroll
            for (int nt = 0; nt < 8; nt++) {
                int bw = (nt * 8 + r0) * 36 + ks * 8 + q;
                uint32_t bh0 = smw[8704 + bw],  bh1 = smw[8704 + bw + 4];
                uint32_t bl0 = smw[11008 + bw], bl1 = smw[11008 + bw + 4];
                mma_bf16(acc[nt], ah0, ah1, ah2, ah3, bh0, bh1);
                mma_bf16(acc[nt], al0, al1, al2, al3, bh0, bh1);
                mma_bf16(acc[nt], ah0, ah1, ah2, ah3, bl0, bl1);
            }
        }
        int n0 = t * 16 + r0, n1 = n0 + 8;
        #pragma unroll
        for (int nt = 0; nt < 8; nt++) {
            int col = nt * 8 + 2 * q;
            float b0 = smf[13376 + col], b1 = smf[13376 + col + 1];
            ((float2*)hout)[(size_t)n0 * 32 + nt * 4 + q] = make_float2(acc[nt][0] + b0, acc[nt][1] + b1);
            ((float2*)hout)[(size_t)n1 * 32 + nt * 4 + q] = make_float2(acc[nt][2] + b0, acc[nt][3] + b1);
        }
        if (lane < 16) {
            int n = t * 16 + lane;
            float cnt = (float)g_hist[n];
            cnt = cnt > 1.f ? cnt : 1.f;
            float inv;
            asm("rcp.approx.f32 %0, %1;" : "=f"(inv) : "f"(cnt));
            cout[n * 3 + 0] = coord[n * 3 + 0] + g_aggc[n * 3 + 0] * inv;
            cout[n * 3 + 1] = coord[n * 3 + 1] + g_aggc[n * 3 + 1] * inv;
            cout[n * 3 + 2] = coord[n * 3 + 2] + g_aggc[n * 3 + 2] * inv;
        }
        __syncwarp();
    }
}

extern "C" void kernel_launch(void* const* d_in, const int* in_sizes, int n_in,
                              void* d_out, int out_size)
{
    const float* h     = (const float*)d_in[0];
    const float* coord = (const float*)d_in[1];
    const void*  ei    = d_in[2];
    const float* emask = (const float*)d_in[3];
    const float* We1 = (const float*)d_in[4];  const float* be1 = (const float*)d_in[5];
    const float* We2 = (const float*)d_in[6];  const float* be2 = (const float*)d_in[7];
    const float* Wn1 = (const float*)d_in[8];  const float* bn1 = (const float*)d_in[9];
    const float* Wn2 = (const float*)d_in[10]; const float* bn2 = (const float*)d_in[11];
    const float* Wc1 = (const float*)d_in[12]; const float* bc1 = (const float*)d_in[13];
    const float* Wc2 = (const float*)d_in[14];

    float* hout = (float*)d_out;
    float* cout = hout + (size_t)NN * 64;

    cudaFuncSetAttribute(scatter_hprep_kernel, cudaFuncAttributeMaxDynamicSharedMemorySize, HP_SMEM_BYTES);
    cudaFuncSetAttribute(edge_kernel, cudaFuncAttributeMaxDynamicSharedMemorySize, SM_EDGE_BYTES);
    cudaFuncSetAttribute(node_kernel, cudaFuncAttributeMaxDynamicSharedMemorySize, ND_SMEM_BYTES);

    zero_kernel<<<2048, 256>>>((const int*)ei);
    hist_kernel<<<1250, 256>>>(ei);
    scan_kernel<<<1, 1024>>>();
    scatter_hprep_kernel<<<HP_BLOCKS + SC_BLOCKS, 256, HP_SMEM_BYTES>>>(ei, emask, coord, h, We1, be1);
    edge_kernel<<<148, 512, SM_EDGE_BYTES>>>(We1, We2, be2, Wc1, bc1, Wc2);
    node_kernel<<<148, 256, ND_SMEM_BYTES>>>(h, coord, Wn1, bn1, Wn2, bn2, hout, cout);
}